// round 12
// baseline (speedup 1.0000x reference)
#include <cuda_runtime.h>
#include <cuda_bf16.h>
#include <cstdint>
#include <cstddef>

#define T_STEPS 2048
#define OFF 8

typedef unsigned long long ull;

// ---------------------------------------------------------------------------
// Device-global tagged history rings: word = {hi32: tag, lo32: f32 h}.
// Global rings use slot = t + OFF, tag = slot + 1.
// ---------------------------------------------------------------------------
__device__ ull g_hist0[(T_STEPS + OFF) * 128];
__device__ ull g_hist1[(T_STEPS + OFF) * 128];
__device__ ull g_hist2[(T_STEPS + OFF) * 128];
__device__ ull g_hist3[(T_STEPS + OFF) * 256];
__device__ float g_zx[(size_t)T_STEPS * 512];   // Wih0@x + bih0 + bhh0

// ---------------------------------------------------------------------------
__device__ __forceinline__ ull ldr(const ull* p) {
    ull v;
    asm volatile("ld.relaxed.gpu.global.u64 %0, [%1];" : "=l"(v) : "l"(p) : "memory");
    return v;
}
__device__ __forceinline__ void str(ull* p, ull v) {
    asm volatile("st.relaxed.gpu.global.u64 [%0], %1;" :: "l"(p), "l"(v) : "memory");
}
__device__ __forceinline__ ull pack_hv(float h, unsigned tag) {
    return ((ull)tag << 32) | (ull)__float_as_uint(h);
}
__device__ __forceinline__ float sigf(float x) {
    return __fdividef(1.0f, 1.0f + __expf(-x));
}
__device__ __forceinline__ float tanh_f(float x) {
    return 2.0f * sigf(2.0f * x) - 1.0f;
}
__device__ __forceinline__ uint32_t smem_u32(const void* p) {
    uint32_t a;
    asm("{ .reg .u64 t; cvta.to.shared.u64 t, %1; cvt.u32.u64 %0, t; }"
        : "=r"(a) : "l"(p));
    return a;
}
// local smem poll (sees remote DSMEM stores)
__device__ __forceinline__ ull lds_vol(uint32_t a) {
    ull v;
    asm volatile("ld.volatile.shared.u64 %0, [%1];" : "=l"(v) : "r"(a) : "memory");
    return v;
}
// remote DSMEM store (address from mapa, shared::cluster window)
__device__ __forceinline__ void sts_cluster(uint32_t a, ull v) {
    asm volatile("st.relaxed.cluster.shared::cluster.u64 [%0], %1;"
                 :: "r"(a), "l"(v) : "memory");
}
__device__ __forceinline__ void cluster_sync_() {
    asm volatile("barrier.cluster.arrive.aligned;" ::: "memory");
    asm volatile("barrier.cluster.wait.aligned;" ::: "memory");
}

// ---------------------------------------------------------------------------
// Init: zero tags, seed initial h states into global rings. Every replay.
// ---------------------------------------------------------------------------
__device__ void init_one(ull* hist, int DOUT, int DIL, const float* h0,
                         int gid, int gs) {
    int N = (T_STEPS + OFF) * DOUT;
    for (int i = gid; i < N; i += gs) {
        int s = i / DOUT;
        int j = i - s * DOUT;
        ull v = 0ull;
        if (s >= OFF - DIL && s < OFF)
            v = pack_hv(h0[(s - (OFF - DIL)) * DOUT + j], (unsigned)(s + 1));
        hist[i] = v;
    }
}

__global__ void init_hist_kernel(const float* __restrict__ h00,
                                 const float* __restrict__ h01,
                                 const float* __restrict__ h02,
                                 const float* __restrict__ h03) {
    int gid = blockIdx.x * blockDim.x + threadIdx.x;
    int gs = gridDim.x * blockDim.x;
    init_one(g_hist0, 128, 1, h00, gid, gs);
    init_one(g_hist1, 128, 2, h01, gid, gs);
    init_one(g_hist2, 128, 4, h02, gid, gs);
    init_one(g_hist3, 256, 8, h03, gid, gs);
}

// ---------------------------------------------------------------------------
// Layer-0 input projection GEMM: g_zx[t][r] = Wih0[r]·x[t] + bih0[r] + bhh0[r]
// ---------------------------------------------------------------------------
__global__ void __launch_bounds__(256) xproj_kernel(const float* __restrict__ x,
                                                    const float* __restrict__ W,
                                                    const float* __restrict__ b1,
                                                    const float* __restrict__ b2) {
    __shared__ float Xs[16][129];
    __shared__ float Ws[16][65];
    const int tid = threadIdx.x;
    const int m0 = blockIdx.x * 128;
    const int n0 = blockIdx.y * 64;
    const int tm = (tid >> 4) * 8;
    const int tn = (tid & 15) * 4;

    float acc[8][4];
#pragma unroll
    for (int i = 0; i < 8; i++)
#pragma unroll
        for (int j = 0; j < 4; j++) acc[i][j] = 0.0f;

    for (int k0 = 0; k0 < 256; k0 += 16) {
#pragma unroll
        for (int i = 0; i < 2; i++) {
            int f = tid + i * 256;
            int m = f >> 2;
            int kq = (f & 3) * 4;
            float4 v = *(const float4*)(x + (size_t)(m0 + m) * 256 + k0 + kq);
            Xs[kq + 0][m] = v.x; Xs[kq + 1][m] = v.y;
            Xs[kq + 2][m] = v.z; Xs[kq + 3][m] = v.w;
        }
        {
            int r = tid >> 2;
            int kq = (tid & 3) * 4;
            float4 v = *(const float4*)(W + (size_t)(n0 + r) * 256 + k0 + kq);
            Ws[kq + 0][r] = v.x; Ws[kq + 1][r] = v.y;
            Ws[kq + 2][r] = v.z; Ws[kq + 3][r] = v.w;
        }
        __syncthreads();
#pragma unroll
        for (int k = 0; k < 16; k++) {
            float rm[8], rn[4];
#pragma unroll
            for (int i = 0; i < 8; i++) rm[i] = Xs[k][tm + i];
#pragma unroll
            for (int j = 0; j < 4; j++) rn[j] = Ws[k][tn + j];
#pragma unroll
            for (int i = 0; i < 8; i++)
#pragma unroll
                for (int j = 0; j < 4; j++)
                    acc[i][j] = fmaf(rm[i], rn[j], acc[i][j]);
        }
        __syncthreads();
    }
#pragma unroll
    for (int i = 0; i < 8; i++)
#pragma unroll
        for (int j = 0; j < 4; j++) {
            int r = n0 + tn + j;
            g_zx[(size_t)(m0 + tm + i) * 512 + r] = acc[i][j] + b1[r] + b2[r];
        }
}

// ---------------------------------------------------------------------------
// Layer 0: 8-CTA cluster, DSMEM 2-slot tagged ring, barrier-free warps.
// Each warp owns 2 h-elems (all 4 gates of each). Lane reads 4 ring words.
// Ring slot(s) = s & 1, tag = s + 2 (s = step of the h value; s=-1 seeds
// slot 1 with tag 1).
//
// Skew-safety of the 2-slot ring: a warp publishes h(t+1) only after it has
// read ALL of h(t); h(t) was published only after every warp had read all of
// h(t-1). Hence when slot (t-1)&1 is overwritten by h(t+1), no reader of
// h(t-1) remains. Exit-safety: the final-step publish is skipped (nobody
// consumes h(T-1) via the ring) and a trailing cluster barrier prevents any
// CTA from exiting while peer DSMEM stores could still be in flight.
// ---------------------------------------------------------------------------
__device__ void run_layer0(int cta,
                           const float* __restrict__ Whh,
                           const float* __restrict__ c0,
                           const float* __restrict__ h0,
                           ull* __restrict__ ring /* smem [2][128] */) {
    const int lane = threadIdx.x & 31;
    const int w    = threadIdx.x >> 5;

    // weights: warp w owns elems {2w, 2w+1}; reg index r = jj*4 + g
    float wreg[8][4];
#pragma unroll
    for (int jj = 0; jj < 2; jj++)
#pragma unroll
        for (int g = 0; g < 4; g++) {
            int zr = g * 128 + cta * 16 + 2 * w + jj;
#pragma unroll
            for (int k = 0; k < 4; k++)
                wreg[jj * 4 + g][k] = Whh[(size_t)zr * 128 + lane + 32 * k];
        }

    // init local ring: slot 1 = h(-1) with tag 1; slot 0 tag 0
    for (int idx = threadIdx.x; idx < 128; idx += 256) {
        ring[128 + idx] = pack_hv(h0[idx], 1u);
        ring[idx] = 0ull;
    }

    // gate lanes (lane 0,1): c-state + peer addresses of owned elem (slot 0)
    const int gelem = cta * 16 + 2 * w + lane;     // valid for lane < 2
    float creg = 0.0f;
    uint32_t peer[8];
    if (lane < 2) {
        creg = c0[gelem];
        uint32_t local = smem_u32(&ring[gelem]);
#pragma unroll
        for (int r = 0; r < 8; r++)
            asm("mapa.shared::cluster.u32 %0, %1, %2;"
                : "=r"(peer[r]) : "r"(local), "r"(r));
    }
    const uint32_t ring_base = smem_u32(ring);

    // all 8 cluster CTAs must finish ring init before any remote store
    cluster_sync_();

    for (int t = 0; t < T_STEPS; t++) {
        // prefetch zx (L2-resident; consumed later at gate phase)
        float zx0 = 0.f, zx1 = 0.f, zx2 = 0.f, zx3 = 0.f;
        if (lane < 2) {
            const float* zp = &g_zx[(size_t)t * 512 + gelem];
            zx0 = __ldg(zp);       zx1 = __ldg(zp + 128);
            zx2 = __ldg(zp + 256); zx3 = __ldg(zp + 384);
        }

        // poll h(t-1) from local ring, slot (t-1)&1, tag t+1
        const uint32_t sbase = ring_base + (((t - 1) & 1) ? 1024u : 0u);
        const unsigned ex = (unsigned)(t + 1);
        ull v[4];
#pragma unroll
        for (int k = 0; k < 4; k++)
            v[k] = lds_vol(sbase + (lane + 32 * k) * 8);
#pragma unroll
        for (int k = 0; k < 4; k++)
            while ((unsigned)(v[k] >> 32) != ex)
                v[k] = lds_vol(sbase + (lane + 32 * k) * 8);

        float acc[8];
#pragma unroll
        for (int r = 0; r < 8; r++) acc[r] = 0.0f;
#pragma unroll
        for (int k = 0; k < 4; k++) {
            float a = __uint_as_float((unsigned)v[k]);
#pragma unroll
            for (int r = 0; r < 8; r++)
                acc[r] = fmaf(wreg[r][k], a, acc[r]);
        }
#pragma unroll
        for (int r = 0; r < 8; r++)
#pragma unroll
            for (int d = 16; d > 0; d >>= 1)
                acc[r] += __shfl_xor_sync(0xffffffffu, acc[r], d);

        if (lane < 2) {
            float zi = (lane ? acc[4] : acc[0]) + zx0;
            float zf = (lane ? acc[5] : acc[1]) + zx1;
            float zg = (lane ? acc[6] : acc[2]) + zx2;
            float zo = (lane ? acc[7] : acc[3]) + zx3;
            float ig = sigf(zi), fg = sigf(zf);
            float gg = tanh_f(zg), og = sigf(zo);
            float c2 = fg * creg + ig * gg;
            creg = c2;
            float h2 = og * tanh_f(c2);

            // ring publish for t < T-1 only (h(T-1) never consumed via ring;
            // skipping it guarantees all remote stores are consumed pre-exit)
            if (t < T_STEPS - 1) {
                ull pk = pack_hv(h2, (unsigned)(t + 2));
                uint32_t soff = (t & 1) ? 1024u : 0u;
#pragma unroll
                for (int r = 0; r < 8; r++)
                    sts_cluster(peer[r] + soff, pk);
            }
            // publish to global ring for layer 1
            str(g_hist0 + (size_t)(t + OFF) * 128 + gelem,
                pack_hv(h2, (unsigned)(t + OFF + 1)));
        }
    }

    // exit-safety: no CTA leaves while peer DSMEM stores may be in flight
    cluster_sync_();
}

// ---------------------------------------------------------------------------
// Upper layers (1..3): barrier-free, per-warp one h-elem, per-lane L2 polls.
// ---------------------------------------------------------------------------
template <int DIN, int DOUT, int G, int DILN, int MODE>
__device__ void run_layer_async(int cta,
                                const float* __restrict__ Wih,
                                const float* __restrict__ Whh,
                                const float* __restrict__ bih,
                                const float* __restrict__ bhh,
                                const float* __restrict__ c0,
                                const ull* __restrict__ hin,
                                ull* __restrict__ hown,
                                float* __restrict__ out) {
    constexpr int CHUNK = DOUT / G;      // 8
    constexpr int COLS  = DIN + DOUT;    // 256 or 384
    constexpr int CPL   = COLS / 32;     // 8 or 12
    static_assert(CHUNK == 8, "8 warps own 8 elems");

    const int lane = threadIdx.x & 31;
    const int w    = threadIdx.x >> 5;
    const int e    = cta * CHUNK + w;    // owned h-elem

    float wreg[4][CPL];
#pragma unroll
    for (int g = 0; g < 4; g++) {
        int zr = g * DOUT + e;
#pragma unroll
        for (int k = 0; k < CPL; k++) {
            int j = lane + 32 * k;
            wreg[g][k] = (j < DIN) ? Wih[(size_t)zr * DIN + j]
                                   : Whh[(size_t)zr * DOUT + (j - DIN)];
        }
    }
    float b0 = 0, b1 = 0, b2 = 0, b3 = 0;
    float creg[DILN];
    if (lane == 0) {
        b0 = bih[0 * DOUT + e] + bhh[0 * DOUT + e];
        b1 = bih[1 * DOUT + e] + bhh[1 * DOUT + e];
        b2 = bih[2 * DOUT + e] + bhh[2 * DOUT + e];
        b3 = bih[3 * DOUT + e] + bhh[3 * DOUT + e];
#pragma unroll
        for (int k = 0; k < DILN; k++) creg[k] = c0[k * DOUT + e];
    }

    for (int tb = 0; tb < T_STEPS; tb += DILN) {
#pragma unroll
        for (int kk = 0; kk < DILN; kk++) {
            const int t = tb + kk;
            const ull* ps[CPL];
            unsigned ex[CPL];
            ull v[CPL];
#pragma unroll
            for (int k = 0; k < CPL; k++) {
                int j = lane + 32 * k;
                if (j < DIN) {
                    ps[k] = hin + (size_t)(t + OFF) * DIN + j;
                    ex[k] = (unsigned)(t + OFF + 1);
                } else {
                    ps[k] = hown + (size_t)(t + OFF - DILN) * DOUT + (j - DIN);
                    ex[k] = (unsigned)(t + OFF - DILN + 1);
                }
                v[k] = ldr(ps[k]);     // batched issue -> MLP
            }
#pragma unroll
            for (int k = 0; k < CPL; k++)
                while ((unsigned)(v[k] >> 32) != ex[k]) v[k] = ldr(ps[k]);

            float a0 = 0, a1 = 0, a2 = 0, a3 = 0;
#pragma unroll
            for (int k = 0; k < CPL; k++) {
                float a = __uint_as_float((unsigned)v[k]);
                a0 = fmaf(wreg[0][k], a, a0);
                a1 = fmaf(wreg[1][k], a, a1);
                a2 = fmaf(wreg[2][k], a, a2);
                a3 = fmaf(wreg[3][k], a, a3);
            }
#pragma unroll
            for (int d = 16; d > 0; d >>= 1) {
                a0 += __shfl_xor_sync(0xffffffffu, a0, d);
                a1 += __shfl_xor_sync(0xffffffffu, a1, d);
                a2 += __shfl_xor_sync(0xffffffffu, a2, d);
                a3 += __shfl_xor_sync(0xffffffffu, a3, d);
            }
            if (lane == 0) {
                float ig = sigf(a0 + b0);
                float fg = sigf(a1 + b1);
                float gg = tanh_f(a2 + b2);
                float og = sigf(a3 + b3);
                float c2 = fg * creg[kk] + ig * gg;   // kk static -> register
                creg[kk] = c2;
                float h2 = og * tanh_f(c2);
                str(hown + (size_t)(t + OFF) * DOUT + e,
                    pack_hv(h2, (unsigned)(t + OFF + 1)));
                if (MODE == 2) out[(size_t)t * 256 + e] = h2;
            }
        }
    }
}

// ---------------------------------------------------------------------------
struct DP {
    const float *Whh0, *h00, *c00;
    const float *Wih1, *Whh1, *bih1, *bhh1, *c01;
    const float *Wih2, *Whh2, *bih2, *bhh2, *c02;
    const float *Wih3, *Whh3, *bih3, *bhh3, *c03;
    float* out;
};

// 72 CTAs, cluster 8: blocks [0,8) = L0 cluster; [8,24)=L1; [24,40)=L2; [40,72)=L3.
__global__ void __launch_bounds__(256, 1) __cluster_dims__(8, 1, 1)
drnn_kernel(DP p) {
    __shared__ ull ring[2 * 128];
    int b = blockIdx.x;
    if (b < 8) {
        run_layer0(b, p.Whh0, p.c00, p.h00, ring);
    } else if (b < 24) {
        run_layer_async<128, 128, 16, 2, 0>(b - 8, p.Wih1, p.Whh1, p.bih1,
                                            p.bhh1, p.c01, g_hist0, g_hist1,
                                            nullptr);
    } else if (b < 40) {
        run_layer_async<128, 128, 16, 4, 0>(b - 24, p.Wih2, p.Whh2, p.bih2,
                                            p.bhh2, p.c02, g_hist1, g_hist2,
                                            nullptr);
    } else {
        run_layer_async<128, 256, 32, 8, 2>(b - 40, p.Wih3, p.Whh3, p.bih3,
                                            p.bhh3, p.c03, g_hist2, g_hist3,
                                            p.out);
    }
}

// ---------------------------------------------------------------------------
extern "C" void kernel_launch(void* const* d_in, const int* in_sizes, int n_in,
                              void* d_out, int out_size) {
    // detect interleaved (x,[W,U,bi,bh,h0,c0]*4) vs grouped (x, W*16, states*8)
    int iW[4], iU[4], ibi[4], ibh[4], ih[4], ic[4];
    if (in_sizes[5] == 128) {            // interleaved
        for (int i = 0; i < 4; i++) {
            int base = 1 + i * 6;
            iW[i] = base; iU[i] = base + 1; ibi[i] = base + 2; ibh[i] = base + 3;
            ih[i] = base + 4; ic[i] = base + 5;
        }
    } else {                             // grouped
        for (int i = 0; i < 4; i++) {
            iW[i] = 1 + 4 * i; iU[i] = 2 + 4 * i;
            ibi[i] = 3 + 4 * i; ibh[i] = 4 + 4 * i;
            ih[i] = 17 + 2 * i; ic[i] = 18 + 2 * i;
        }
    }

    const float* x = (const float*)d_in[0];

    init_hist_kernel<<<256, 256>>>((const float*)d_in[ih[0]],
                                   (const float*)d_in[ih[1]],
                                   (const float*)d_in[ih[2]],
                                   (const float*)d_in[ih[3]]);

    dim3 g(16, 8);
    xproj_kernel<<<g, 256>>>(x, (const float*)d_in[iW[0]],
                             (const float*)d_in[ibi[0]],
                             (const float*)d_in[ibh[0]]);

    DP p;
    p.Whh0 = (const float*)d_in[iU[0]];
    p.h00  = (const float*)d_in[ih[0]];
    p.c00  = (const float*)d_in[ic[0]];
    p.Wih1 = (const float*)d_in[iW[1]]; p.Whh1 = (const float*)d_in[iU[1]];
    p.bih1 = (const float*)d_in[ibi[1]]; p.bhh1 = (const float*)d_in[ibh[1]];
    p.c01  = (const float*)d_in[ic[1]];
    p.Wih2 = (const float*)d_in[iW[2]]; p.Whh2 = (const float*)d_in[iU[2]];
    p.bih2 = (const float*)d_in[ibi[2]]; p.bhh2 = (const float*)d_in[ibh[2]];
    p.c02  = (const float*)d_in[ic[2]];
    p.Wih3 = (const float*)d_in[iW[3]]; p.Whh3 = (const float*)d_in[iU[3]];
    p.bih3 = (const float*)d_in[ibi[3]]; p.bhh3 = (const float*)d_in[ibh[3]];
    p.c03  = (const float*)d_in[ic[3]];
    p.out  = (float*)d_out;

    drnn_kernel<<<72, 256>>>(p);
}

// round 13
// speedup vs baseline: 1.0060x; 1.0060x over previous
#include <cuda_runtime.h>
#include <cuda_bf16.h>
#include <cstdint>
#include <cstddef>

#define T_STEPS 2048
#define OFF 8

typedef unsigned long long ull;

// ---------------------------------------------------------------------------
// Device-global tagged history rings: word = {hi32: tag, lo32: f32 h}.
// Global rings: slot = t + OFF, tag = slot + 1.
// ---------------------------------------------------------------------------
__device__ ull g_hist0[(T_STEPS + OFF) * 128];
__device__ ull g_hist1[(T_STEPS + OFF) * 128];
__device__ ull g_hist2[(T_STEPS + OFF) * 128];
__device__ ull g_hist3[(T_STEPS + OFF) * 256];
__device__ float g_zx[(size_t)T_STEPS * 512];   // Wih0@x + bih0 + bhh0

// ---------------------------------------------------------------------------
__device__ __forceinline__ ull ldr(const ull* p) {
    ull v;
    asm volatile("ld.relaxed.gpu.global.u64 %0, [%1];" : "=l"(v) : "l"(p) : "memory");
    return v;
}
__device__ __forceinline__ void str(ull* p, ull v) {
    asm volatile("st.relaxed.gpu.global.u64 [%0], %1;" :: "l"(p), "l"(v) : "memory");
}
__device__ __forceinline__ ull pack_hv(float h, unsigned tag) {
    return ((ull)tag << 32) | (ull)__float_as_uint(h);
}
__device__ __forceinline__ float sigf(float x) {
    return __fdividef(1.0f, 1.0f + __expf(-x));
}
__device__ __forceinline__ float tanh_f(float x) {
    return 2.0f * sigf(2.0f * x) - 1.0f;
}
__device__ __forceinline__ uint32_t smem_u32(const void* p) {
    uint32_t a;
    asm("{ .reg .u64 t; cvta.to.shared.u64 t, %1; cvt.u32.u64 %0, t; }"
        : "=r"(a) : "l"(p));
    return a;
}
__device__ __forceinline__ ull lds_vol(uint32_t a) {
    ull v;
    asm volatile("ld.volatile.shared.u64 %0, [%1];" : "=l"(v) : "r"(a) : "memory");
    return v;
}
__device__ __forceinline__ void sts_cluster(uint32_t a, ull v) {
    asm volatile("st.relaxed.cluster.shared::cluster.u64 [%0], %1;"
                 :: "r"(a), "l"(v) : "memory");
}
__device__ __forceinline__ void cluster_sync_() {
    asm volatile("barrier.cluster.arrive.aligned;" ::: "memory");
    asm volatile("barrier.cluster.wait.aligned;" ::: "memory");
}

// ---------------------------------------------------------------------------
// Init: zero tags, seed initial h states into global rings. Every replay.
// ---------------------------------------------------------------------------
__device__ void init_one(ull* hist, int DOUT, int DIL, const float* h0,
                         int gid, int gs) {
    int N = (T_STEPS + OFF) * DOUT;
    for (int i = gid; i < N; i += gs) {
        int s = i / DOUT;
        int j = i - s * DOUT;
        ull v = 0ull;
        if (s >= OFF - DIL && s < OFF)
            v = pack_hv(h0[(s - (OFF - DIL)) * DOUT + j], (unsigned)(s + 1));
        hist[i] = v;
    }
}

__global__ void init_hist_kernel(const float* __restrict__ h00,
                                 const float* __restrict__ h01,
                                 const float* __restrict__ h02,
                                 const float* __restrict__ h03) {
    int gid = blockIdx.x * blockDim.x + threadIdx.x;
    int gs = gridDim.x * blockDim.x;
    init_one(g_hist0, 128, 1, h00, gid, gs);
    init_one(g_hist1, 128, 2, h01, gid, gs);
    init_one(g_hist2, 128, 4, h02, gid, gs);
    init_one(g_hist3, 256, 8, h03, gid, gs);
}

// ---------------------------------------------------------------------------
// Layer-0 input projection GEMM: g_zx[t][r] = Wih0[r]·x[t] + bih0[r] + bhh0[r]
// ---------------------------------------------------------------------------
__global__ void __launch_bounds__(256) xproj_kernel(const float* __restrict__ x,
                                                    const float* __restrict__ W,
                                                    const float* __restrict__ b1,
                                                    const float* __restrict__ b2) {
    __shared__ float Xs[16][129];
    __shared__ float Ws[16][65];
    const int tid = threadIdx.x;
    const int m0 = blockIdx.x * 128;
    const int n0 = blockIdx.y * 64;
    const int tm = (tid >> 4) * 8;
    const int tn = (tid & 15) * 4;

    float acc[8][4];
#pragma unroll
    for (int i = 0; i < 8; i++)
#pragma unroll
        for (int j = 0; j < 4; j++) acc[i][j] = 0.0f;

    for (int k0 = 0; k0 < 256; k0 += 16) {
#pragma unroll
        for (int i = 0; i < 2; i++) {
            int f = tid + i * 256;
            int m = f >> 2;
            int kq = (f & 3) * 4;
            float4 v = *(const float4*)(x + (size_t)(m0 + m) * 256 + k0 + kq);
            Xs[kq + 0][m] = v.x; Xs[kq + 1][m] = v.y;
            Xs[kq + 2][m] = v.z; Xs[kq + 3][m] = v.w;
        }
        {
            int r = tid >> 2;
            int kq = (tid & 3) * 4;
            float4 v = *(const float4*)(W + (size_t)(n0 + r) * 256 + k0 + kq);
            Ws[kq + 0][r] = v.x; Ws[kq + 1][r] = v.y;
            Ws[kq + 2][r] = v.z; Ws[kq + 3][r] = v.w;
        }
        __syncthreads();
#pragma unroll
        for (int k = 0; k < 16; k++) {
            float rm[8], rn[4];
#pragma unroll
            for (int i = 0; i < 8; i++) rm[i] = Xs[k][tm + i];
#pragma unroll
            for (int j = 0; j < 4; j++) rn[j] = Ws[k][tn + j];
#pragma unroll
            for (int i = 0; i < 8; i++)
#pragma unroll
                for (int j = 0; j < 4; j++)
                    acc[i][j] = fmaf(rm[i], rn[j], acc[i][j]);
        }
        __syncthreads();
    }
#pragma unroll
    for (int i = 0; i < 8; i++)
#pragma unroll
        for (int j = 0; j < 4; j++) {
            int r = n0 + tn + j;
            g_zx[(size_t)(m0 + tm + i) * 512 + r] = acc[i][j] + b1[r] + b2[r];
        }
}

// ---------------------------------------------------------------------------
// Layer 0: 8-CTA cluster, DSMEM 2-slot tagged ring, barrier-free warps.
// Warp owns 2 h-elems (all 4 gates of each); lane 0/1 computes gates.
// Ring slot = s & 1, tag = s + 2 (h(-1) seeds slot 1, tag 1).
// Skew-safe: publishing h(t+1) requires having read all h(t), which required
// all warps to have published h(t), which required them to have read h(t-1);
// so the h(t-1) slot has no live readers when overwritten. Exit-safe: final
// publish skipped + trailing cluster barrier.
// ---------------------------------------------------------------------------
__device__ void run_layer0(int cta,
                           const float* __restrict__ Whh,
                           const float* __restrict__ c0,
                           const float* __restrict__ h0,
                           ull* __restrict__ ring /* smem [2][128] */) {
    const int lane = threadIdx.x & 31;
    const int w    = threadIdx.x >> 5;

    float wreg[8][4];                    // r = jj*4 + g
#pragma unroll
    for (int jj = 0; jj < 2; jj++)
#pragma unroll
        for (int g = 0; g < 4; g++) {
            int zr = g * 128 + cta * 16 + 2 * w + jj;
#pragma unroll
            for (int k = 0; k < 4; k++)
                wreg[jj * 4 + g][k] = Whh[(size_t)zr * 128 + lane + 32 * k];
        }

    for (int idx = threadIdx.x; idx < 128; idx += 256) {
        ring[128 + idx] = pack_hv(h0[idx], 1u);
        ring[idx] = 0ull;
    }

    const int gelem = cta * 16 + 2 * w + lane;   // valid for lane < 2
    float creg = 0.0f;
    uint32_t peer[8];
    if (lane < 2) {
        creg = c0[gelem];
        uint32_t local = smem_u32(&ring[gelem]);
#pragma unroll
        for (int r = 0; r < 8; r++)
            asm("mapa.shared::cluster.u32 %0, %1, %2;"
                : "=r"(peer[r]) : "r"(local), "r"(r));
    }
    const uint32_t ring_base = smem_u32(ring);

    cluster_sync_();                    // ring init visible before remote stores

    for (int t = 0; t < T_STEPS; t++) {
        float zx0 = 0.f, zx1 = 0.f, zx2 = 0.f, zx3 = 0.f;
        if (lane < 2) {
            const float* zp = &g_zx[(size_t)t * 512 + gelem];
            zx0 = __ldg(zp);       zx1 = __ldg(zp + 128);
            zx2 = __ldg(zp + 256); zx3 = __ldg(zp + 384);
        }

        const uint32_t sbase = ring_base + (((t - 1) & 1) ? 1024u : 0u);
        const unsigned ex = (unsigned)(t + 1);
        ull v[4];
#pragma unroll
        for (int k = 0; k < 4; k++)
            v[k] = lds_vol(sbase + (lane + 32 * k) * 8);
#pragma unroll
        for (int k = 0; k < 4; k++)
            while ((unsigned)(v[k] >> 32) != ex)
                v[k] = lds_vol(sbase + (lane + 32 * k) * 8);

        float acc[8];
#pragma unroll
        for (int r = 0; r < 8; r++) acc[r] = 0.0f;
#pragma unroll
        for (int k = 0; k < 4; k++) {
            float a = __uint_as_float((unsigned)v[k]);
#pragma unroll
            for (int r = 0; r < 8; r++)
                acc[r] = fmaf(wreg[r][k], a, acc[r]);
        }
#pragma unroll
        for (int r = 0; r < 8; r++)
#pragma unroll
            for (int d = 16; d > 0; d >>= 1)
                acc[r] += __shfl_xor_sync(0xffffffffu, acc[r], d);

        if (lane < 2) {
            float zi = (lane ? acc[4] : acc[0]) + zx0;
            float zf = (lane ? acc[5] : acc[1]) + zx1;
            float zg = (lane ? acc[6] : acc[2]) + zx2;
            float zo = (lane ? acc[7] : acc[3]) + zx3;
            float ig = sigf(zi), fg = sigf(zf);
            float gg = tanh_f(zg), og = sigf(zo);
            float c2 = fg * creg + ig * gg;
            creg = c2;
            float h2 = og * tanh_f(c2);

            if (t < T_STEPS - 1) {
                ull pk = pack_hv(h2, (unsigned)(t + 2));
                uint32_t soff = (t & 1) ? 1024u : 0u;
#pragma unroll
                for (int r = 0; r < 8; r++)
                    sts_cluster(peer[r] + soff, pk);
            }
            str(g_hist0 + (size_t)(t + OFF) * 128 + gelem,
                pack_hv(h2, (unsigned)(t + OFF + 1)));
        }
    }

    cluster_sync_();                    // no exit with peer stores in flight
}

// ---------------------------------------------------------------------------
// Upper layers (1..3): cooperative staging (ONE L2 load per word per CTA) into
// a double-buffered smem act[] — single __syncthreads per step. Warp owns
// 2 h-elems (gate-in-warp mapping); lane 0/1 does gates; c-state in smem
// slots private to the gate lane.
//
// Single-barrier safety: the writer of act buffer (t&1) at step t has passed
// bar(t-1), which required every thread to finish staging step t-1, which is
// after its step t-2 reads of buffer (t&1) (consumers precede the barrier in
// program order). So no live reader exists when a buffer is overwritten.
// ---------------------------------------------------------------------------
template <int DIN, int DOUT, int G, int DILN, int MODE>
__device__ void run_layer_coop(int cta,
                               const float* __restrict__ Wih,
                               const float* __restrict__ Whh,
                               const float* __restrict__ bih,
                               const float* __restrict__ bhh,
                               const float* __restrict__ c0,
                               const ull* __restrict__ hin,
                               ull* __restrict__ hown,
                               float* __restrict__ out,
                               float* __restrict__ act,  /* [2][COLS] */
                               float* __restrict__ csh   /* [DILN*CHUNK] */) {
    constexpr int CHUNK = DOUT / G;       // 16
    constexpr int COLS  = DIN + DOUT;     // 256 or 384
    constexpr int CPL   = COLS / 32;      // 8 or 12
    static_assert(CHUNK == 16, "8 warps x 2 elems");

    const int tid  = threadIdx.x;
    const int lane = tid & 31;
    const int w    = tid >> 5;

    // weight slice: warp w owns elems {2w, 2w+1}; r = jj*4 + g
    float wreg[8][CPL];
#pragma unroll
    for (int jj = 0; jj < 2; jj++)
#pragma unroll
        for (int g = 0; g < 4; g++) {
            int zr = g * DOUT + cta * CHUNK + 2 * w + jj;
#pragma unroll
            for (int k = 0; k < CPL; k++) {
                int j = lane + 32 * k;
                wreg[jj * 4 + g][k] = (j < DIN)
                    ? Wih[(size_t)zr * DIN + j]
                    : Whh[(size_t)zr * DOUT + (j - DIN)];
            }
        }

    const int gelem = cta * CHUNK + 2 * w + lane;   // valid for lane < 2
    float b[4] = {0.f, 0.f, 0.f, 0.f};
    if (lane < 2) {
#pragma unroll
        for (int g = 0; g < 4; g++)
            b[g] = bih[g * DOUT + gelem] + bhh[g * DOUT + gelem];
        for (int k = 0; k < DILN; k++)
            csh[k * CHUNK + 2 * w + lane] = c0[k * DOUT + gelem];
    }
    __syncthreads();

    for (int t = 0; t < T_STEPS; t++) {
        float* buf = act + (t & 1) * COLS;
        // cooperative staging: poll each word once per CTA
        for (int idx = tid; idx < COLS; idx += 256) {
            const ull* p;
            unsigned ex;
            if (idx < DIN) {
                p  = hin + (size_t)(t + OFF) * DIN + idx;
                ex = (unsigned)(t + OFF + 1);
            } else {
                p  = hown + (size_t)(t + OFF - DILN) * DOUT + (idx - DIN);
                ex = (unsigned)(t + OFF - DILN + 1);
            }
            ull v = ldr(p);
            while ((unsigned)(v >> 32) != ex) v = ldr(p);
            buf[idx] = __uint_as_float((unsigned)v);
        }
        __syncthreads();

        float acc[8];
#pragma unroll
        for (int r = 0; r < 8; r++) acc[r] = 0.0f;
#pragma unroll
        for (int k = 0; k < CPL; k++) {
            float a = buf[lane + 32 * k];
#pragma unroll
            for (int r = 0; r < 8; r++)
                acc[r] = fmaf(wreg[r][k], a, acc[r]);
        }
#pragma unroll
        for (int r = 0; r < 8; r++)
#pragma unroll
            for (int d = 16; d > 0; d >>= 1)
                acc[r] += __shfl_xor_sync(0xffffffffu, acc[r], d);

        if (lane < 2) {
            float zi = (lane ? acc[4] : acc[0]) + b[0];
            float zf = (lane ? acc[5] : acc[1]) + b[1];
            float zg = (lane ? acc[6] : acc[2]) + b[2];
            float zo = (lane ? acc[7] : acc[3]) + b[3];
            float ig = sigf(zi), fg = sigf(zf);
            float gg = tanh_f(zg), og = sigf(zo);
            int ci = (t & (DILN - 1)) * CHUNK + 2 * w + lane;
            float c2 = fg * csh[ci] + ig * gg;
            csh[ci] = c2;
            float h2 = og * tanh_f(c2);
            str(hown + (size_t)(t + OFF) * DOUT + gelem,
                pack_hv(h2, (unsigned)(t + OFF + 1)));
            if (MODE == 2) out[(size_t)t * 256 + gelem] = h2;
        }
    }
}

// ---------------------------------------------------------------------------
struct DP {
    const float *Whh0, *h00, *c00;
    const float *Wih1, *Whh1, *bih1, *bhh1, *c01;
    const float *Wih2, *Whh2, *bih2, *bhh2, *c02;
    const float *Wih3, *Whh3, *bih3, *bhh3, *c03;
    float* out;
};

// 40 CTAs, cluster 8: [0,8)=L0 cluster; [8,16)=L1; [16,24)=L2; [24,40)=L3.
__global__ void __launch_bounds__(256, 1) __cluster_dims__(8, 1, 1)
drnn_kernel(DP p) {
    __shared__ ull  ring[2 * 128];
    __shared__ float act[2 * 384];
    __shared__ float csh[8 * 16];
    int b = blockIdx.x;
    if (b < 8) {
        run_layer0(b, p.Whh0, p.c00, p.h00, ring);
    } else if (b < 16) {
        run_layer_coop<128, 128, 8, 2, 0>(b - 8, p.Wih1, p.Whh1, p.bih1,
                                          p.bhh1, p.c01, g_hist0, g_hist1,
                                          nullptr, act, csh);
    } else if (b < 24) {
        run_layer_coop<128, 128, 8, 4, 0>(b - 16, p.Wih2, p.Whh2, p.bih2,
                                          p.bhh2, p.c02, g_hist1, g_hist2,
                                          nullptr, act, csh);
    } else {
        run_layer_coop<128, 256, 16, 8, 2>(b - 24, p.Wih3, p.Whh3, p.bih3,
                                           p.bhh3, p.c03, g_hist2, g_hist3,
                                           p.out, act, csh);
    }
}

// ---------------------------------------------------------------------------
extern "C" void kernel_launch(void* const* d_in, const int* in_sizes, int n_in,
                              void* d_out, int out_size) {
    // detect interleaved (x,[W,U,bi,bh,h0,c0]*4) vs grouped (x, W*16, states*8)
    int iW[4], iU[4], ibi[4], ibh[4], ih[4], ic[4];
    if (in_sizes[5] == 128) {            // interleaved
        for (int i = 0; i < 4; i++) {
            int base = 1 + i * 6;
            iW[i] = base; iU[i] = base + 1; ibi[i] = base + 2; ibh[i] = base + 3;
            ih[i] = base + 4; ic[i] = base + 5;
        }
    } else {                             // grouped
        for (int i = 0; i < 4; i++) {
            iW[i] = 1 + 4 * i; iU[i] = 2 + 4 * i;
            ibi[i] = 3 + 4 * i; ibh[i] = 4 + 4 * i;
            ih[i] = 17 + 2 * i; ic[i] = 18 + 2 * i;
        }
    }

    const float* x = (const float*)d_in[0];

    init_hist_kernel<<<256, 256>>>((const float*)d_in[ih[0]],
                                   (const float*)d_in[ih[1]],
                                   (const float*)d_in[ih[2]],
                                   (const float*)d_in[ih[3]]);

    dim3 g(16, 8);
    xproj_kernel<<<g, 256>>>(x, (const float*)d_in[iW[0]],
                             (const float*)d_in[ibi[0]],
                             (const float*)d_in[ibh[0]]);

    DP p;
    p.Whh0 = (const float*)d_in[iU[0]];
    p.h00  = (const float*)d_in[ih[0]];
    p.c00  = (const float*)d_in[ic[0]];
    p.Wih1 = (const float*)d_in[iW[1]]; p.Whh1 = (const float*)d_in[iU[1]];
    p.bih1 = (const float*)d_in[ibi[1]]; p.bhh1 = (const float*)d_in[ibh[1]];
    p.c01  = (const float*)d_in[ic[1]];
    p.Wih2 = (const float*)d_in[iW[2]]; p.Whh2 = (const float*)d_in[iU[2]];
    p.bih2 = (const float*)d_in[ibi[2]]; p.bhh2 = (const float*)d_in[ibh[2]];
    p.c02  = (const float*)d_in[ic[2]];
    p.Wih3 = (const float*)d_in[iW[3]]; p.Whh3 = (const float*)d_in[iU[3]];
    p.bih3 = (const float*)d_in[ibi[3]]; p.bhh3 = (const float*)d_in[ibh[3]];
    p.c03  = (const float*)d_in[ic[3]];
    p.out  = (float*)d_out;

    drnn_kernel<<<40, 256>>>(p);
}

// round 14
// speedup vs baseline: 5.9709x; 5.9351x over previous
#include <cuda_runtime.h>
#include <cuda_bf16.h>
#include <cstdint>
#include <cstddef>

#define T_STEPS 2048
#define OFF 8

typedef unsigned long long ull;

// ---------------------------------------------------------------------------
// Device-global tagged history rings: word = {hi32: tag, lo32: f32 h}.
// Global rings: slot = t + OFF, tag = slot + 1.
// ---------------------------------------------------------------------------
__device__ ull g_hist0[(T_STEPS + OFF) * 128];
__device__ ull g_hist1[(T_STEPS + OFF) * 128];
__device__ ull g_hist2[(T_STEPS + OFF) * 128];
__device__ ull g_hist3[(T_STEPS + OFF) * 256];
__device__ float g_zx[(size_t)T_STEPS * 512];   // Wih0@x + bih0 + bhh0

// ---------------------------------------------------------------------------
__device__ __forceinline__ ull ldr(const ull* p) {
    ull v;
    asm volatile("ld.relaxed.gpu.global.u64 %0, [%1];" : "=l"(v) : "l"(p) : "memory");
    return v;
}
__device__ __forceinline__ void str(ull* p, ull v) {
    asm volatile("st.relaxed.gpu.global.u64 [%0], %1;" :: "l"(p), "l"(v) : "memory");
}
__device__ __forceinline__ ull pack_hv(float h, unsigned tag) {
    return ((ull)tag << 32) | (ull)__float_as_uint(h);
}
__device__ __forceinline__ float sigf(float x) {
    return __fdividef(1.0f, 1.0f + __expf(-x));
}
__device__ __forceinline__ float tanh_f(float x) {
    return 2.0f * sigf(2.0f * x) - 1.0f;
}
__device__ __forceinline__ uint32_t smem_u32(const void* p) {
    uint32_t a;
    asm("{ .reg .u64 t; cvta.to.shared.u64 t, %1; cvt.u32.u64 %0, t; }"
        : "=r"(a) : "l"(p));
    return a;
}
__device__ __forceinline__ ull lds_vol(uint32_t a) {
    ull v;
    asm volatile("ld.volatile.shared.u64 %0, [%1];" : "=l"(v) : "r"(a) : "memory");
    return v;
}
__device__ __forceinline__ void sts_cluster(uint32_t a, ull v) {
    asm volatile("st.relaxed.cluster.shared::cluster.u64 [%0], %1;"
                 :: "r"(a), "l"(v) : "memory");
}
__device__ __forceinline__ void cluster_sync_() {
    asm volatile("barrier.cluster.arrive.aligned;" ::: "memory");
    asm volatile("barrier.cluster.wait.aligned;" ::: "memory");
}
// Blackwell packed f32x2 FMA / ADD
__device__ __forceinline__ ull fma2_(ull a, ull b, ull c) {
    ull d;
    asm("fma.rn.f32x2 %0, %1, %2, %3;" : "=l"(d) : "l"(a), "l"(b), "l"(c));
    return d;
}
__device__ __forceinline__ ull add2_(ull a, ull b) {
    ull d;
    asm("add.rn.f32x2 %0, %1, %2;" : "=l"(d) : "l"(a), "l"(b));
    return d;
}

// ---------------------------------------------------------------------------
// Init: zero tags, seed initial h states into global rings. Every replay.
// ---------------------------------------------------------------------------
__device__ void init_one(ull* hist, int DOUT, int DIL, const float* h0,
                         int gid, int gs) {
    int N = (T_STEPS + OFF) * DOUT;
    for (int i = gid; i < N; i += gs) {
        int s = i / DOUT;
        int j = i - s * DOUT;
        ull v = 0ull;
        if (s >= OFF - DIL && s < OFF)
            v = pack_hv(h0[(s - (OFF - DIL)) * DOUT + j], (unsigned)(s + 1));
        hist[i] = v;
    }
}

__global__ void init_hist_kernel(const float* __restrict__ h00,
                                 const float* __restrict__ h01,
                                 const float* __restrict__ h02,
                                 const float* __restrict__ h03) {
    int gid = blockIdx.x * blockDim.x + threadIdx.x;
    int gs = gridDim.x * blockDim.x;
    init_one(g_hist0, 128, 1, h00, gid, gs);
    init_one(g_hist1, 128, 2, h01, gid, gs);
    init_one(g_hist2, 128, 4, h02, gid, gs);
    init_one(g_hist3, 256, 8, h03, gid, gs);
}

// ---------------------------------------------------------------------------
// Layer-0 input projection GEMM: g_zx[t][r] = Wih0[r]·x[t] + bih0[r] + bhh0[r]
// ---------------------------------------------------------------------------
__global__ void __launch_bounds__(256) xproj_kernel(const float* __restrict__ x,
                                                    const float* __restrict__ W,
                                                    const float* __restrict__ b1,
                                                    const float* __restrict__ b2) {
    __shared__ float Xs[16][129];
    __shared__ float Ws[16][65];
    const int tid = threadIdx.x;
    const int m0 = blockIdx.x * 128;
    const int n0 = blockIdx.y * 64;
    const int tm = (tid >> 4) * 8;
    const int tn = (tid & 15) * 4;

    float acc[8][4];
#pragma unroll
    for (int i = 0; i < 8; i++)
#pragma unroll
        for (int j = 0; j < 4; j++) acc[i][j] = 0.0f;

    for (int k0 = 0; k0 < 256; k0 += 16) {
#pragma unroll
        for (int i = 0; i < 2; i++) {
            int f = tid + i * 256;
            int m = f >> 2;
            int kq = (f & 3) * 4;
            float4 v = *(const float4*)(x + (size_t)(m0 + m) * 256 + k0 + kq);
            Xs[kq + 0][m] = v.x; Xs[kq + 1][m] = v.y;
            Xs[kq + 2][m] = v.z; Xs[kq + 3][m] = v.w;
        }
        {
            int r = tid >> 2;
            int kq = (tid & 3) * 4;
            float4 v = *(const float4*)(W + (size_t)(n0 + r) * 256 + k0 + kq);
            Ws[kq + 0][r] = v.x; Ws[kq + 1][r] = v.y;
            Ws[kq + 2][r] = v.z; Ws[kq + 3][r] = v.w;
        }
        __syncthreads();
#pragma unroll
        for (int k = 0; k < 16; k++) {
            float rm[8], rn[4];
#pragma unroll
            for (int i = 0; i < 8; i++) rm[i] = Xs[k][tm + i];
#pragma unroll
            for (int j = 0; j < 4; j++) rn[j] = Ws[k][tn + j];
#pragma unroll
            for (int i = 0; i < 8; i++)
#pragma unroll
                for (int j = 0; j < 4; j++)
                    acc[i][j] = fmaf(rm[i], rn[j], acc[i][j]);
        }
        __syncthreads();
    }
#pragma unroll
    for (int i = 0; i < 8; i++)
#pragma unroll
        for (int j = 0; j < 4; j++) {
            int r = n0 + tn + j;
            g_zx[(size_t)(m0 + tm + i) * 512 + r] = acc[i][j] + b1[r] + b2[r];
        }
}

// ---------------------------------------------------------------------------
// Layer 0: 2-CTA cluster. CTA rank owns elems [64*rank, 64*rank+64) = 256
// z-rows; thread tid owns row (tid>>6)*128 + 64*rank + (tid&63), weights in
// 128 registers as 64 packed f32x2. GEMV reads full h(t-1) from smem via
// broadcast. Exchange: 64 tagged words to the peer's ring (slot t&1, tag
// t+2); ONLY warp 7 polls (2 words/lane) to avoid smem-port spin saturation.
// Step 0 reads h(-1) directly from the h0 input (no seeding). Final-step
// ring publish skipped + trailing cluster barrier for exit safety.
// ---------------------------------------------------------------------------
__device__ void run_layer0_pair(int rank,
                                const float* __restrict__ Whh,
                                const float* __restrict__ c0,
                                const float* __restrict__ h0,
                                ull* __restrict__ ring,   /* smem [2][64] */
                                float* __restrict__ act,  /* smem [128]   */
                                float* __restrict__ zsh   /* smem [256]   */) {
    const int tid = threadIdx.x;
    const int lane = tid & 31;
    const int w = tid >> 5;
    const int gate = tid >> 6;           // 0..3
    const int el = tid & 63;             // local elem index
    const int e = 64 * rank + el;        // global elem of this thread's row
    const int zr = gate * 128 + e;       // owned z-row

    // ---- pack weight row into 64 f32x2 registers ----
    ull wr[64];
#pragma unroll
    for (int j = 0; j < 64; j++) {
        float lo = Whh[(size_t)zr * 128 + 2 * j];
        float hi = Whh[(size_t)zr * 128 + 2 * j + 1];
        wr[j] = (ull)__float_as_uint(lo) | ((ull)__float_as_uint(hi) << 32);
    }

    // zero ring tags (smem is stale across launches)
    if (tid < 128) ring[tid] = 0ull;

    // gate threads (tid < 64): c-state + peer ring address for own word
    float creg = 0.0f;
    uint32_t peer_addr = 0;
    if (tid < 64) {
        creg = c0[e];
        uint32_t local = smem_u32(&ring[el]);      // slot 0, word el
        asm("mapa.shared::cluster.u32 %0, %1, %2;"
            : "=r"(peer_addr) : "r"(local), "r"(1 - rank));
    }
    const uint32_t ring_base = smem_u32(ring);
    __syncthreads();
    cluster_sync_();        // ring zeroing visible before any remote store

    const ull* hv = (const ull*)act;

    for (int t = 0; t < T_STEPS; t++) {
        // prefetch zx for gate threads (L2-resident, consumed after GEMV)
        float zx0 = 0.f, zx1 = 0.f, zx2 = 0.f, zx3 = 0.f;
        if (tid < 64) {
            const float* zp = &g_zx[(size_t)t * 512 + e];
            zx0 = __ldg(zp);       zx1 = __ldg(zp + 128);
            zx2 = __ldg(zp + 256); zx3 = __ldg(zp + 384);
        }

        // ---- phase 1: assemble act = h(t-1) ----
        if (t == 0) {
            for (int i = tid; i < 128; i += 256) act[i] = h0[i];
        } else if (w == 7) {
            // poll peer half: slot (t-1)&1, tag t+1; 2 words per lane
            const uint32_t sb = ring_base + (((t - 1) & 1) ? 512u : 0u);
            const unsigned ex = (unsigned)(t + 1);
            ull v0 = lds_vol(sb + lane * 8);
            ull v1 = lds_vol(sb + (lane + 32) * 8);
            while ((unsigned)(v0 >> 32) != ex) v0 = lds_vol(sb + lane * 8);
            while ((unsigned)(v1 >> 32) != ex) v1 = lds_vol(sb + (lane + 32) * 8);
            act[64 * (1 - rank) + lane]      = __uint_as_float((unsigned)v0);
            act[64 * (1 - rank) + lane + 32] = __uint_as_float((unsigned)v1);
        }
        __syncthreads();

        // ---- phase 2: GEMV z[zr] = Whh[zr] · h(t-1), packed f32x2 ----
        ull a0 = 0, a1 = 0, a2 = 0, a3 = 0;
#pragma unroll
        for (int j = 0; j < 64; j += 4) {
            a0 = fma2_(wr[j + 0], hv[j + 0], a0);
            a1 = fma2_(wr[j + 1], hv[j + 1], a1);
            a2 = fma2_(wr[j + 2], hv[j + 2], a2);
            a3 = fma2_(wr[j + 3], hv[j + 3], a3);
        }
        ull s = add2_(add2_(a0, a1), add2_(a2, a3));
        zsh[tid] = __uint_as_float((unsigned)s) +
                   __uint_as_float((unsigned)(s >> 32));
        __syncthreads();

        // ---- phase 3: gates (tid < 64) + publish ----
        if (tid < 64) {
            float zi = zsh[el]        + zx0;
            float zf = zsh[64 + el]   + zx1;
            float zg = zsh[128 + el]  + zx2;
            float zo = zsh[192 + el]  + zx3;
            float ig = sigf(zi), fg = sigf(zf);
            float gg = tanh_f(zg), og = sigf(zo);
            float c2 = fg * creg + ig * gg;
            creg = c2;
            float h2 = og * tanh_f(c2);

            act[e] = h2;                            // own half for next GEMV
            if (t < T_STEPS - 1)                    // peer ring publish
                sts_cluster(peer_addr + ((t & 1) ? 512u : 0u),
                            pack_hv(h2, (unsigned)(t + 2)));
            str(g_hist0 + (size_t)(t + OFF) * 128 + e,   // for layer 1
                pack_hv(h2, (unsigned)(t + OFF + 1)));
        }
    }

    cluster_sync_();        // no exit while peer stores may be in flight
}

// ---------------------------------------------------------------------------
// Upper layers (1..3): cooperative staging (one L2 load per word per CTA)
// into double-buffered smem act[]; single __syncthreads per step; warp owns
// 2 h-elems (gate-in-warp mapping); lane 0/1 does gates; c in smem.
// ---------------------------------------------------------------------------
template <int DIN, int DOUT, int G, int DILN, int MODE>
__device__ void run_layer_coop(int cta,
                               const float* __restrict__ Wih,
                               const float* __restrict__ Whh,
                               const float* __restrict__ bih,
                               const float* __restrict__ bhh,
                               const float* __restrict__ c0,
                               const ull* __restrict__ hin,
                               ull* __restrict__ hown,
                               float* __restrict__ out,
                               float* __restrict__ act,  /* [2][COLS] */
                               float* __restrict__ csh   /* [DILN*CHUNK] */) {
    constexpr int CHUNK = DOUT / G;       // 16
    constexpr int COLS  = DIN + DOUT;     // 256 or 384
    constexpr int CPL   = COLS / 32;      // 8 or 12
    static_assert(CHUNK == 16, "8 warps x 2 elems");

    const int tid  = threadIdx.x;
    const int lane = tid & 31;
    const int w    = tid >> 5;

    float wreg[8][CPL];
#pragma unroll
    for (int jj = 0; jj < 2; jj++)
#pragma unroll
        for (int g = 0; g < 4; g++) {
            int zr = g * DOUT + cta * CHUNK + 2 * w + jj;
#pragma unroll
            for (int k = 0; k < CPL; k++) {
                int j = lane + 32 * k;
                wreg[jj * 4 + g][k] = (j < DIN)
                    ? Wih[(size_t)zr * DIN + j]
                    : Whh[(size_t)zr * DOUT + (j - DIN)];
            }
        }

    const int gelem = cta * CHUNK + 2 * w + lane;   // valid for lane < 2
    float b[4] = {0.f, 0.f, 0.f, 0.f};
    if (lane < 2) {
#pragma unroll
        for (int g = 0; g < 4; g++)
            b[g] = bih[g * DOUT + gelem] + bhh[g * DOUT + gelem];
        for (int k = 0; k < DILN; k++)
            csh[k * CHUNK + 2 * w + lane] = c0[k * DOUT + gelem];
    }
    __syncthreads();

    for (int t = 0; t < T_STEPS; t++) {
        float* buf = act + (t & 1) * COLS;
        for (int idx = tid; idx < COLS; idx += 256) {
            const ull* p;
            unsigned ex;
            if (idx < DIN) {
                p  = hin + (size_t)(t + OFF) * DIN + idx;
                ex = (unsigned)(t + OFF + 1);
            } else {
                p  = hown + (size_t)(t + OFF - DILN) * DOUT + (idx - DIN);
                ex = (unsigned)(t + OFF - DILN + 1);
            }
            ull v = ldr(p);
            while ((unsigned)(v >> 32) != ex) v = ldr(p);
            buf[idx] = __uint_as_float((unsigned)v);
        }
        __syncthreads();

        float acc[8];
#pragma unroll
        for (int r = 0; r < 8; r++) acc[r] = 0.0f;
#pragma unroll
        for (int k = 0; k < CPL; k++) {
            float a = buf[lane + 32 * k];
#pragma unroll
            for (int r = 0; r < 8; r++)
                acc[r] = fmaf(wreg[r][k], a, acc[r]);
        }
#pragma unroll
        for (int r = 0; r < 8; r++)
#pragma unroll
            for (int d = 16; d > 0; d >>= 1)
                acc[r] += __shfl_xor_sync(0xffffffffu, acc[r], d);

        if (lane < 2) {
            float zi = (lane ? acc[4] : acc[0]) + b[0];
            float zf = (lane ? acc[5] : acc[1]) + b[1];
            float zg = (lane ? acc[6] : acc[2]) + b[2];
            float zo = (lane ? acc[7] : acc[3]) + b[3];
            float ig = sigf(zi), fg = sigf(zf);
            float gg = tanh_f(zg), og = sigf(zo);
            int ci = (t & (DILN - 1)) * CHUNK + 2 * w + lane;
            float c2 = fg * csh[ci] + ig * gg;
            csh[ci] = c2;
            float h2 = og * tanh_f(c2);
            str(hown + (size_t)(t + OFF) * DOUT + gelem,
                pack_hv(h2, (unsigned)(t + OFF + 1)));
            if (MODE == 2) out[(size_t)t * 256 + gelem] = h2;
        }
    }
}

// ---------------------------------------------------------------------------
struct DP {
    const float *Whh0, *h00, *c00;
    const float *Wih1, *Whh1, *bih1, *bhh1, *c01;
    const float *Wih2, *Whh2, *bih2, *bhh2, *c02;
    const float *Wih3, *Whh3, *bih3, *bhh3, *c03;
    float* out;
};

// 34 CTAs, cluster 2: {0,1}=L0 pair; [2,10)=L1; [10,18)=L2; [18,34)=L3.
__global__ void __launch_bounds__(256, 1) __cluster_dims__(2, 1, 1)
drnn_kernel(DP p) {
    __shared__ ull   ring[2 * 64];
    __shared__ float act0[128];
    __shared__ float zsh[256];
    __shared__ float act[2 * 384];
    __shared__ float csh[8 * 16];
    int b = blockIdx.x;
    if (b < 2) {
        run_layer0_pair(b, p.Whh0, p.c00, p.h00, ring, act0, zsh);
    } else if (b < 10) {
        run_layer_coop<128, 128, 8, 2, 0>(b - 2, p.Wih1, p.Whh1, p.bih1,
                                          p.bhh1, p.c01, g_hist0, g_hist1,
                                          nullptr, act, csh);
    } else if (b < 18) {
        run_layer_coop<128, 128, 8, 4, 0>(b - 10, p.Wih2, p.Whh2, p.bih2,
                                          p.bhh2, p.c02, g_hist1, g_hist2,
                                          nullptr, act, csh);
    } else {
        run_layer_coop<128, 256, 16, 8, 2>(b - 18, p.Wih3, p.Whh3, p.bih3,
                                           p.bhh3, p.c03, g_hist2, g_hist3,
                                           p.out, act, csh);
    }
}

// ---------------------------------------------------------------------------
extern "C" void kernel_launch(void* const* d_in, const int* in_sizes, int n_in,
                              void* d_out, int out_size) {
    // detect interleaved (x,[W,U,bi,bh,h0,c0]*4) vs grouped (x, W*16, states*8)
    int iW[4], iU[4], ibi[4], ibh[4], ih[4], ic[4];
    if (in_sizes[5] == 128) {            // interleaved
        for (int i = 0; i < 4; i++) {
            int base = 1 + i * 6;
            iW[i] = base; iU[i] = base + 1; ibi[i] = base + 2; ibh[i] = base + 3;
            ih[i] = base + 4; ic[i] = base + 5;
        }
    } else {                             // grouped
        for (int i = 0; i < 4; i++) {
            iW[i] = 1 + 4 * i; iU[i] = 2 + 4 * i;
            ibi[i] = 3 + 4 * i; ibh[i] = 4 + 4 * i;
            ih[i] = 17 + 2 * i; ic[i] = 18 + 2 * i;
        }
    }

    const float* x = (const float*)d_in[0];

    init_hist_kernel<<<256, 256>>>((const float*)d_in[ih[0]],
                                   (const float*)d_in[ih[1]],
                                   (const float*)d_in[ih[2]],
                                   (const float*)d_in[ih[3]]);

    dim3 g(16, 8);
    xproj_kernel<<<g, 256>>>(x, (const float*)d_in[iW[0]],
                             (const float*)d_in[ibi[0]],
                             (const float*)d_in[ibh[0]]);

    DP p;
    p.Whh0 = (const float*)d_in[iU[0]];
    p.h00  = (const float*)d_in[ih[0]];
    p.c00  = (const float*)d_in[ic[0]];
    p.Wih1 = (const float*)d_in[iW[1]]; p.Whh1 = (const float*)d_in[iU[1]];
    p.bih1 = (const float*)d_in[ibi[1]]; p.bhh1 = (const float*)d_in[ibh[1]];
    p.c01  = (const float*)d_in[ic[1]];
    p.Wih2 = (const float*)d_in[iW[2]]; p.Whh2 = (const float*)d_in[iU[2]];
    p.bih2 = (const float*)d_in[ibi[2]]; p.bhh2 = (const float*)d_in[ibh[2]];
    p.c02  = (const float*)d_in[ic[2]];
    p.Wih3 = (const float*)d_in[iW[3]]; p.Whh3 = (const float*)d_in[iU[3]];
    p.bih3 = (const float*)d_in[ibi[3]]; p.bhh3 = (const float*)d_in[ibh[3]];
    p.c03  = (const float*)d_in[ic[3]];
    p.out  = (float*)d_out;

    drnn_kernel<<<34, 256>>>(p);
}

// round 15
// speedup vs baseline: 6.8692x; 1.1504x over previous
#include <cuda_runtime.h>
#include <cuda_bf16.h>
#include <cstdint>
#include <cstddef>

#define T_STEPS 2048
#define OFF 8

typedef unsigned long long ull;

// ---------------------------------------------------------------------------
// Device-global tagged history rings: word = {hi32: tag, lo32: f32 h}.
// Global rings: slot = t + OFF, tag = slot + 1.
// ---------------------------------------------------------------------------
__device__ ull g_hist0[(T_STEPS + OFF) * 128];
__device__ ull g_hist1[(T_STEPS + OFF) * 128];
__device__ ull g_hist2[(T_STEPS + OFF) * 128];
__device__ ull g_hist3[(T_STEPS + OFF) * 256];
__device__ float g_zx[(size_t)T_STEPS * 512];   // Wih0@x + bih0 + bhh0

// ---------------------------------------------------------------------------
__device__ __forceinline__ ull ldr(const ull* p) {
    ull v;
    asm volatile("ld.relaxed.gpu.global.u64 %0, [%1];" : "=l"(v) : "l"(p) : "memory");
    return v;
}
__device__ __forceinline__ void str(ull* p, ull v) {
    asm volatile("st.relaxed.gpu.global.u64 [%0], %1;" :: "l"(p), "l"(v) : "memory");
}
__device__ __forceinline__ ull pack_hv(float h, unsigned tag) {
    return ((ull)tag << 32) | (ull)__float_as_uint(h);
}
__device__ __forceinline__ float sigf(float x) {
    return __fdividef(1.0f, 1.0f + __expf(-x));
}
__device__ __forceinline__ float tanh_f(float x) {
    return 2.0f * sigf(2.0f * x) - 1.0f;
}
__device__ __forceinline__ uint32_t smem_u32(const void* p) {
    uint32_t a;
    asm("{ .reg .u64 t; cvta.to.shared.u64 t, %1; cvt.u32.u64 %0, t; }"
        : "=r"(a) : "l"(p));
    return a;
}
__device__ __forceinline__ ull lds_vol(uint32_t a) {
    ull v;
    asm volatile("ld.volatile.shared.u64 %0, [%1];" : "=l"(v) : "r"(a) : "memory");
    return v;
}
__device__ __forceinline__ void sts_cluster(uint32_t a, ull v) {
    asm volatile("st.relaxed.cluster.shared::cluster.u64 [%0], %1;"
                 :: "r"(a), "l"(v) : "memory");
}
__device__ __forceinline__ void cluster_sync_() {
    asm volatile("barrier.cluster.arrive.aligned;" ::: "memory");
    asm volatile("barrier.cluster.wait.aligned;" ::: "memory");
}
// Blackwell packed f32x2 FMA
__device__ __forceinline__ ull fma2_(ull a, ull b, ull c) {
    ull d;
    asm("fma.rn.f32x2 %0, %1, %2, %3;" : "=l"(d) : "l"(a), "l"(b), "l"(c));
    return d;
}

// ---------------------------------------------------------------------------
// Init: zero tags, seed initial h states into global rings. Every replay.
// ---------------------------------------------------------------------------
__device__ void init_one(ull* hist, int DOUT, int DIL, const float* h0,
                         int gid, int gs) {
    int N = (T_STEPS + OFF) * DOUT;
    for (int i = gid; i < N; i += gs) {
        int s = i / DOUT;
        int j = i - s * DOUT;
        ull v = 0ull;
        if (s >= OFF - DIL && s < OFF)
            v = pack_hv(h0[(s - (OFF - DIL)) * DOUT + j], (unsigned)(s + 1));
        hist[i] = v;
    }
}

__global__ void init_hist_kernel(const float* __restrict__ h00,
                                 const float* __restrict__ h01,
                                 const float* __restrict__ h02,
                                 const float* __restrict__ h03) {
    int gid = blockIdx.x * blockDim.x + threadIdx.x;
    int gs = gridDim.x * blockDim.x;
    init_one(g_hist0, 128, 1, h00, gid, gs);
    init_one(g_hist1, 128, 2, h01, gid, gs);
    init_one(g_hist2, 128, 4, h02, gid, gs);
    init_one(g_hist3, 256, 8, h03, gid, gs);
}

// ---------------------------------------------------------------------------
// Layer-0 input projection GEMM: g_zx[t][r] = Wih0[r]·x[t] + bih0[r] + bhh0[r]
// ---------------------------------------------------------------------------
__global__ void __launch_bounds__(256) xproj_kernel(const float* __restrict__ x,
                                                    const float* __restrict__ W,
                                                    const float* __restrict__ b1,
                                                    const float* __restrict__ b2) {
    __shared__ float Xs[16][129];
    __shared__ float Ws[16][65];
    const int tid = threadIdx.x;
    const int m0 = blockIdx.x * 128;
    const int n0 = blockIdx.y * 64;
    const int tm = (tid >> 4) * 8;
    const int tn = (tid & 15) * 4;

    float acc[8][4];
#pragma unroll
    for (int i = 0; i < 8; i++)
#pragma unroll
        for (int j = 0; j < 4; j++) acc[i][j] = 0.0f;

    for (int k0 = 0; k0 < 256; k0 += 16) {
#pragma unroll
        for (int i = 0; i < 2; i++) {
            int f = tid + i * 256;
            int m = f >> 2;
            int kq = (f & 3) * 4;
            float4 v = *(const float4*)(x + (size_t)(m0 + m) * 256 + k0 + kq);
            Xs[kq + 0][m] = v.x; Xs[kq + 1][m] = v.y;
            Xs[kq + 2][m] = v.z; Xs[kq + 3][m] = v.w;
        }
        {
            int r = tid >> 2;
            int kq = (tid & 3) * 4;
            float4 v = *(const float4*)(W + (size_t)(n0 + r) * 256 + k0 + kq);
            Ws[kq + 0][r] = v.x; Ws[kq + 1][r] = v.y;
            Ws[kq + 2][r] = v.z; Ws[kq + 3][r] = v.w;
        }
        __syncthreads();
#pragma unroll
        for (int k = 0; k < 16; k++) {
            float rm[8], rn[4];
#pragma unroll
            for (int i = 0; i < 8; i++) rm[i] = Xs[k][tm + i];
#pragma unroll
            for (int j = 0; j < 4; j++) rn[j] = Ws[k][tn + j];
#pragma unroll
            for (int i = 0; i < 8; i++)
#pragma unroll
                for (int j = 0; j < 4; j++)
                    acc[i][j] = fmaf(rm[i], rn[j], acc[i][j]);
        }
        __syncthreads();
    }
#pragma unroll
    for (int i = 0; i < 8; i++)
#pragma unroll
        for (int j = 0; j < 4; j++) {
            int r = n0 + tn + j;
            g_zx[(size_t)(m0 + tm + i) * 512 + r] = acc[i][j] + b1[r] + b2[r];
        }
}

// ---------------------------------------------------------------------------
// Layer 0: 2-CTA cluster, split-GEMV with DSMEM-transit overlap, fused gates.
//
// CTA rank owns elems [64r, 64r+64). Warp w owns 8 elems {64r+8w+0..7}.
// Lane l: elem x = l&7 (global e = 64r+8w+x), col-chunk c = l>>3 (4 chunks).
// Lane holds, for each of the 4 gate rows of its elem, 16 own-half cols
// [64r+16c, +16) and 16 peer-half cols [64(1-r)+16c, +16) as packed f32x2.
//
// Step: bar1 -> own-half FMA (overlaps peer DSMEM transit) ; warp7 polls
// peer ring, writes act peer half -> bar2 -> peer-half FMA -> 2-level
// shfl_xor(8,16) butterfly combines the 4 chunks -> lanes 0..7 compute gates
// in registers (c-state register-resident), write act own word, publish to
// peer ring (skip final step) + g_hist0.
//
// Ring: [2][64] words, slot = t&1, tag = t+2; reader at t polls slot (t-1)&1
// for tag t+1. 2-slot overwrite and exit safety as proven in R11/R14.
// ---------------------------------------------------------------------------
__device__ void run_layer0_pair(int rank,
                                const float* __restrict__ Whh,
                                const float* __restrict__ c0,
                                const float* __restrict__ h0,
                                ull* __restrict__ ring,   /* smem [2][64] */
                                float* __restrict__ act   /* smem [128], 16B aligned */) {
    const int tid  = threadIdx.x;
    const int lane = tid & 31;
    const int w    = tid >> 5;
    const int x    = lane & 7;        // elem-in-warp
    const int c    = lane >> 3;       // col chunk 0..3
    const int e    = 64 * rank + 8 * w + x;   // global elem (gate lanes: lane<8 -> c==0)

    // ---- pack weights: 4 gates x (8 own + 8 peer) f32x2 ----
    ull wo[4][8], wp[4][8];
    const int ownb  = 64 * rank + 16 * c;
    const int peerb = 64 * (1 - rank) + 16 * c;
#pragma unroll
    for (int g = 0; g < 4; g++) {
        const float* row = Whh + (size_t)(g * 128 + e) * 128;
#pragma unroll
        for (int k = 0; k < 8; k++) {
            wo[g][k] = (ull)__float_as_uint(row[ownb + 2 * k]) |
                       ((ull)__float_as_uint(row[ownb + 2 * k + 1]) << 32);
            wp[g][k] = (ull)__float_as_uint(row[peerb + 2 * k]) |
                       ((ull)__float_as_uint(row[peerb + 2 * k + 1]) << 32);
        }
    }

    // ---- init: zero ring, stage act = h(-1) ----
    if (tid < 128) ring[tid] = 0ull;
    if (tid < 128) act[tid] = h0[tid];

    float creg = 0.0f;
    uint32_t peer_addr = 0;
    if (lane < 8) {
        creg = c0[e];
        uint32_t local = smem_u32(&ring[8 * w + x]);   // own word, slot 0
        asm("mapa.shared::cluster.u32 %0, %1, %2;"
            : "=r"(peer_addr) : "r"(local), "r"(1 - rank));
    }
    const uint32_t ring_base = smem_u32(ring);
    __syncthreads();
    cluster_sync_();                  // ring zero + act visible before stores

    const ull* hv = (const ull*)act;  // 64 packed f32x2
    const int ou = ownb >> 1;         // own chunk start in hv
    const int pu = peerb >> 1;

    for (int t = 0; t < T_STEPS; t++) {
        // prefetch zx for gate lanes (L2-resident; consumed at gate phase)
        float zx0 = 0.f, zx1 = 0.f, zx2 = 0.f, zx3 = 0.f;
        if (lane < 8) {
            const float* zp = &g_zx[(size_t)t * 512 + e];
            zx0 = __ldg(zp);       zx1 = __ldg(zp + 128);
            zx2 = __ldg(zp + 256); zx3 = __ldg(zp + 384);
        }

        __syncthreads();              // bar1: act own half (t-1) visible

        // ---- own-half FMA (overlaps peer DSMEM transit) ----
        ull a0 = 0, a1 = 0, a2 = 0, a3 = 0;
        {
            ull h[8];
#pragma unroll
            for (int k = 0; k < 4; k++)
                ((ulonglong2*)h)[k] = ((const ulonglong2*)(hv + ou))[k];
#pragma unroll
            for (int k = 0; k < 8; k++) {
                a0 = fma2_(wo[0][k], h[k], a0);
                a1 = fma2_(wo[1][k], h[k], a1);
                a2 = fma2_(wo[2][k], h[k], a2);
                a3 = fma2_(wo[3][k], h[k], a3);
            }
        }

        // warp 7: poll peer half (2 words/lane), write act peer half
        if (w == 7 && t > 0) {
            const uint32_t sb = ring_base + (((t - 1) & 1) ? 512u : 0u);
            const unsigned ex = (unsigned)(t + 1);
            ull v0 = lds_vol(sb + lane * 8);
            ull v1 = lds_vol(sb + (lane + 32) * 8);
            while ((unsigned)(v0 >> 32) != ex) v0 = lds_vol(sb + lane * 8);
            while ((unsigned)(v1 >> 32) != ex) v1 = lds_vol(sb + (lane + 32) * 8);
            act[64 * (1 - rank) + lane]      = __uint_as_float((unsigned)v0);
            act[64 * (1 - rank) + lane + 32] = __uint_as_float((unsigned)v1);
        }

        __syncthreads();              // bar2: act peer half (t-1) visible

        // ---- peer-half FMA ----
        {
            ull h[8];
#pragma unroll
            for (int k = 0; k < 4; k++)
                ((ulonglong2*)h)[k] = ((const ulonglong2*)(hv + pu))[k];
#pragma unroll
            for (int k = 0; k < 8; k++) {
                a0 = fma2_(wp[0][k], h[k], a0);
                a1 = fma2_(wp[1][k], h[k], a1);
                a2 = fma2_(wp[2][k], h[k], a2);
                a3 = fma2_(wp[3][k], h[k], a3);
            }
        }

        // horizontal lo+hi, then butterfly over the 4 col chunks
        float s0 = __uint_as_float((unsigned)a0) + __uint_as_float((unsigned)(a0 >> 32));
        float s1 = __uint_as_float((unsigned)a1) + __uint_as_float((unsigned)(a1 >> 32));
        float s2 = __uint_as_float((unsigned)a2) + __uint_as_float((unsigned)(a2 >> 32));
        float s3 = __uint_as_float((unsigned)a3) + __uint_as_float((unsigned)(a3 >> 32));
        s0 += __shfl_xor_sync(0xffffffffu, s0, 8);
        s1 += __shfl_xor_sync(0xffffffffu, s1, 8);
        s2 += __shfl_xor_sync(0xffffffffu, s2, 8);
        s3 += __shfl_xor_sync(0xffffffffu, s3, 8);
        s0 += __shfl_xor_sync(0xffffffffu, s0, 16);
        s1 += __shfl_xor_sync(0xffffffffu, s1, 16);
        s2 += __shfl_xor_sync(0xffffffffu, s2, 16);
        s3 += __shfl_xor_sync(0xffffffffu, s3, 16);

        // ---- gates in lanes 0..7, all in registers ----
        if (lane < 8) {
            float ig = sigf(s0 + zx0);
            float fg = sigf(s1 + zx1);
            float gg = tanh_f(s2 + zx2);
            float og = sigf(s3 + zx3);
            float c2 = fg * creg + ig * gg;
            creg = c2;
            float h2 = og * tanh_f(c2);

            act[e] = h2;                            // own half for next step
            if (t < T_STEPS - 1)
                sts_cluster(peer_addr + ((t & 1) ? 512u : 0u),
                            pack_hv(h2, (unsigned)(t + 2)));
            str(g_hist0 + (size_t)(t + OFF) * 128 + e,
                pack_hv(h2, (unsigned)(t + OFF + 1)));
        }
    }

    cluster_sync_();                  // exit safety: peer stores consumed
}

// ---------------------------------------------------------------------------
// Upper layers (1..3): coop staging into double-buffered smem (1 bar/step),
// warp owns ONE elem (CHUNK=8), c-state register-resident in lane 0 with the
// t-loop unrolled by DILN so indices stay static.
// ---------------------------------------------------------------------------
template <int DIN, int DOUT, int G, int DILN, int MODE>
__device__ void run_layer_coop(int cta,
                               const float* __restrict__ Wih,
                               const float* __restrict__ Whh,
                               const float* __restrict__ bih,
                               const float* __restrict__ bhh,
                               const float* __restrict__ c0,
                               const ull* __restrict__ hin,
                               ull* __restrict__ hown,
                               float* __restrict__ out,
                               float* __restrict__ act /* [2][COLS] */) {
    constexpr int CHUNK = DOUT / G;       // 8
    constexpr int COLS  = DIN + DOUT;     // 256 or 384
    constexpr int CPL   = COLS / 32;      // 8 or 12
    static_assert(CHUNK == 8, "8 warps x 1 elem");

    const int tid  = threadIdx.x;
    const int lane = tid & 31;
    const int w    = tid >> 5;
    const int e    = cta * CHUNK + w;     // owned h-elem

    float wreg[4][CPL];
#pragma unroll
    for (int g = 0; g < 4; g++) {
        int zr = g * DOUT + e;
#pragma unroll
        for (int k = 0; k < CPL; k++) {
            int j = lane + 32 * k;
            wreg[g][k] = (j < DIN) ? Wih[(size_t)zr * DIN + j]
                                   : Whh[(size_t)zr * DOUT + (j - DIN)];
        }
    }
    float b0 = 0, b1 = 0, b2 = 0, b3 = 0;
    float creg[DILN];
    if (lane == 0) {
        b0 = bih[0 * DOUT + e] + bhh[0 * DOUT + e];
        b1 = bih[1 * DOUT + e] + bhh[1 * DOUT + e];
        b2 = bih[2 * DOUT + e] + bhh[2 * DOUT + e];
        b3 = bih[3 * DOUT + e] + bhh[3 * DOUT + e];
#pragma unroll
        for (int k = 0; k < DILN; k++) creg[k] = c0[k * DOUT + e];
    }

    for (int tb = 0; tb < T_STEPS; tb += DILN) {
#pragma unroll
        for (int kk = 0; kk < DILN; kk++) {
            const int t = tb + kk;
            float* buf = act + (t & 1) * COLS;
            // cooperative staging: one tagged L2 load per word per CTA
            for (int idx = tid; idx < COLS; idx += 256) {
                const ull* p;
                unsigned ex;
                if (idx < DIN) {
                    p  = hin + (size_t)(t + OFF) * DIN + idx;
                    ex = (unsigned)(t + OFF + 1);
                } else {
                    p  = hown + (size_t)(t + OFF - DILN) * DOUT + (idx - DIN);
                    ex = (unsigned)(t + OFF - DILN + 1);
                }
                ull v = ldr(p);
                while ((unsigned)(v >> 32) != ex) v = ldr(p);
                buf[idx] = __uint_as_float((unsigned)v);
            }
            __syncthreads();

            float a0 = 0, a1 = 0, a2 = 0, a3 = 0;
#pragma unroll
            for (int k = 0; k < CPL; k++) {
                float a = buf[lane + 32 * k];
                a0 = fmaf(wreg[0][k], a, a0);
                a1 = fmaf(wreg[1][k], a, a1);
                a2 = fmaf(wreg[2][k], a, a2);
                a3 = fmaf(wreg[3][k], a, a3);
            }
#pragma unroll
            for (int d = 16; d > 0; d >>= 1) {
                a0 += __shfl_xor_sync(0xffffffffu, a0, d);
                a1 += __shfl_xor_sync(0xffffffffu, a1, d);
                a2 += __shfl_xor_sync(0xffffffffu, a2, d);
                a3 += __shfl_xor_sync(0xffffffffu, a3, d);
            }
            if (lane == 0) {
                float ig = sigf(a0 + b0);
                float fg = sigf(a1 + b1);
                float gg = tanh_f(a2 + b2);
                float og = sigf(a3 + b3);
                float c2 = fg * creg[kk] + ig * gg;   // static index
                creg[kk] = c2;
                float h2 = og * tanh_f(c2);
                str(hown + (size_t)(t + OFF) * DOUT + e,
                    pack_hv(h2, (unsigned)(t + OFF + 1)));
                if (MODE == 2) out[(size_t)t * 256 + e] = h2;
            }
        }
    }
}

// ---------------------------------------------------------------------------
struct DP {
    const float *Whh0, *h00, *c00;
    const float *Wih1, *Whh1, *bih1, *bhh1, *c01;
    const float *Wih2, *Whh2, *bih2, *bhh2, *c02;
    const float *Wih3, *Whh3, *bih3, *bhh3, *c03;
    float* out;
};

// 66 CTAs, cluster 2: {0,1}=L0 pair; [2,18)=L1; [18,34)=L2; [34,66)=L3.
__global__ void __launch_bounds__(256, 1) __cluster_dims__(2, 1, 1)
drnn_kernel(DP p) {
    __shared__ ull ring[2 * 64];
    __shared__ __align__(16) float act0[128];
    __shared__ float act[2 * 384];
    int b = blockIdx.x;
    if (b < 2) {
        run_layer0_pair(b, p.Whh0, p.c00, p.h00, ring, act0);
    } else if (b < 18) {
        run_layer_coop<128, 128, 16, 2, 0>(b - 2, p.Wih1, p.Whh1, p.bih1,
                                           p.bhh1, p.c01, g_hist0, g_hist1,
                                           nullptr, act);
    } else if (b < 34) {
        run_layer_coop<128, 128, 16, 4, 0>(b - 18, p.Wih2, p.Whh2, p.bih2,
                                           p.bhh2, p.c02, g_hist1, g_hist2,
                                           nullptr, act);
    } else {
        run_layer_coop<128, 256, 32, 8, 2>(b - 34, p.Wih3, p.Whh3, p.bih3,
                                           p.bhh3, p.c03, g_hist2, g_hist3,
                                           p.out, act);
    }
}

// ---------------------------------------------------------------------------
extern "C" void kernel_launch(void* const* d_in, const int* in_sizes, int n_in,
                              void* d_out, int out_size) {
    // detect interleaved (x,[W,U,bi,bh,h0,c0]*4) vs grouped (x, W*16, states*8)
    int iW[4], iU[4], ibi[4], ibh[4], ih[4], ic[4];
    if (in_sizes[5] == 128) {            // interleaved
        for (int i = 0; i < 4; i++) {
            int base = 1 + i * 6;
            iW[i] = base; iU[i] = base + 1; ibi[i] = base + 2; ibh[i] = base + 3;
            ih[i] = base + 4; ic[i] = base + 5;
        }
    } else {                             // grouped
        for (int i = 0; i < 4; i++) {
            iW[i] = 1 + 4 * i; iU[i] = 2 + 4 * i;
            ibi[i] = 3 + 4 * i; ibh[i] = 4 + 4 * i;
            ih[i] = 17 + 2 * i; ic[i] = 18 + 2 * i;
        }
    }

    const float* x = (const float*)d_in[0];

    init_hist_kernel<<<256, 256>>>((const float*)d_in[ih[0]],
                                   (const float*)d_in[ih[1]],
                                   (const float*)d_in[ih[2]],
                                   (const float*)d_in[ih[3]]);

    dim3 g(16, 8);
    xproj_kernel<<<g, 256>>>(x, (const float*)d_in[iW[0]],
                             (const float*)d_in[ibi[0]],
                             (const float*)d_in[ibh[0]]);

    DP p;
    p.Whh0 = (const float*)d_in[iU[0]];
    p.h00  = (const float*)d_in[ih[0]];
    p.c00  = (const float*)d_in[ic[0]];
    p.Wih1 = (const float*)d_in[iW[1]]; p.Whh1 = (const float*)d_in[iU[1]];
    p.bih1 = (const float*)d_in[ibi[1]]; p.bhh1 = (const float*)d_in[ibh[1]];
    p.c01  = (const float*)d_in[ic[1]];
    p.Wih2 = (const float*)d_in[iW[2]]; p.Whh2 = (const float*)d_in[iU[2]];
    p.bih2 = (const float*)d_in[ibi[2]]; p.bhh2 = (const float*)d_in[ibh[2]];
    p.c02  = (const float*)d_in[ic[2]];
    p.Wih3 = (const float*)d_in[iW[3]]; p.Whh3 = (const float*)d_in[iU[3]];
    p.bih3 = (const float*)d_in[ibi[3]]; p.bhh3 = (const float*)d_in[ibh[3]];
    p.c03  = (const float*)d_in[ic[3]];
    p.out  = (float*)d_out;

    drnn_kernel<<<66, 256>>>(p);
}

// round 16
// speedup vs baseline: 12.7571x; 1.8572x over previous
#include <cuda_runtime.h>
#include <cuda_bf16.h>
#include <cstdint>
#include <cstddef>

#define T_STEPS 2048
#define OFF 8

typedef unsigned long long ull;

// ---------------------------------------------------------------------------
// Device-global tagged history rings (+1 slot so prestage reads stay in
// bounds): word = {hi32: tag, lo32: f32 h}. slot = t + OFF, tag = slot + 1.
// ---------------------------------------------------------------------------
__device__ ull g_hist0[(T_STEPS + OFF + 1) * 128];
__device__ ull g_hist1[(T_STEPS + OFF + 1) * 128];
__device__ ull g_hist2[(T_STEPS + OFF + 1) * 128];
__device__ ull g_hist3[(T_STEPS + OFF + 1) * 256];
__device__ float g_zx[(size_t)T_STEPS * 512];   // Wih0@x + bih0 + bhh0

// ---------------------------------------------------------------------------
__device__ __forceinline__ ull ldr(const ull* p) {
    ull v;
    asm volatile("ld.relaxed.gpu.global.u64 %0, [%1];" : "=l"(v) : "l"(p) : "memory");
    return v;
}
__device__ __forceinline__ void str(ull* p, ull v) {
    asm volatile("st.relaxed.gpu.global.u64 [%0], %1;" :: "l"(p), "l"(v) : "memory");
}
__device__ __forceinline__ ull pack_hv(float h, unsigned tag) {
    return ((ull)tag << 32) | (ull)__float_as_uint(h);
}
// fast activations: single-MUFU tanh, sigmoid via tanh identity
__device__ __forceinline__ float tanh_ap(float x) {
    float y;
    asm("tanh.approx.f32 %0, %1;" : "=f"(y) : "f"(x));
    return y;
}
__device__ __forceinline__ float sig_ap(float x) {
    return fmaf(0.5f, tanh_ap(0.5f * x), 0.5f);
}
__device__ __forceinline__ uint32_t smem_u32(const void* p) {
    uint32_t a;
    asm("{ .reg .u64 t; cvta.to.shared.u64 t, %1; cvt.u32.u64 %0, t; }"
        : "=r"(a) : "l"(p));
    return a;
}
__device__ __forceinline__ ull lds_vol(uint32_t a) {
    ull v;
    asm volatile("ld.volatile.shared.u64 %0, [%1];" : "=l"(v) : "r"(a) : "memory");
    return v;
}
__device__ __forceinline__ void sts_cluster(uint32_t a, ull v) {
    asm volatile("st.relaxed.cluster.shared::cluster.u64 [%0], %1;"
                 :: "r"(a), "l"(v) : "memory");
}
__device__ __forceinline__ void cluster_sync_() {
    asm volatile("barrier.cluster.arrive.aligned;" ::: "memory");
    asm volatile("barrier.cluster.wait.aligned;" ::: "memory");
}
__device__ __forceinline__ ull fma2_(ull a, ull b, ull c) {
    ull d;
    asm("fma.rn.f32x2 %0, %1, %2, %3;" : "=l"(d) : "l"(a), "l"(b), "l"(c));
    return d;
}

// ---------------------------------------------------------------------------
// Init: zero tags (incl. the +1 spare slot), seed initial h. Every replay.
// ---------------------------------------------------------------------------
__device__ void init_one(ull* hist, int DOUT, int DIL, const float* h0,
                         int gid, int gs) {
    int N = (T_STEPS + OFF + 1) * DOUT;
    for (int i = gid; i < N; i += gs) {
        int s = i / DOUT;
        int j = i - s * DOUT;
        ull v = 0ull;
        if (s >= OFF - DIL && s < OFF)
            v = pack_hv(h0[(s - (OFF - DIL)) * DOUT + j], (unsigned)(s + 1));
        hist[i] = v;
    }
}

__global__ void init_hist_kernel(const float* __restrict__ h00,
                                 const float* __restrict__ h01,
                                 const float* __restrict__ h02,
                                 const float* __restrict__ h03) {
    int gid = blockIdx.x * blockDim.x + threadIdx.x;
    int gs = gridDim.x * blockDim.x;
    init_one(g_hist0, 128, 1, h00, gid, gs);
    init_one(g_hist1, 128, 2, h01, gid, gs);
    init_one(g_hist2, 128, 4, h02, gid, gs);
    init_one(g_hist3, 256, 8, h03, gid, gs);
}

// ---------------------------------------------------------------------------
// Layer-0 input projection GEMM: g_zx[t][r] = Wih0[r]·x[t] + bih0[r] + bhh0[r]
// ---------------------------------------------------------------------------
__global__ void __launch_bounds__(256) xproj_kernel(const float* __restrict__ x,
                                                    const float* __restrict__ W,
                                                    const float* __restrict__ b1,
                                                    const float* __restrict__ b2) {
    __shared__ float Xs[16][129];
    __shared__ float Ws[16][65];
    const int tid = threadIdx.x;
    const int m0 = blockIdx.x * 128;
    const int n0 = blockIdx.y * 64;
    const int tm = (tid >> 4) * 8;
    const int tn = (tid & 15) * 4;

    float acc[8][4];
#pragma unroll
    for (int i = 0; i < 8; i++)
#pragma unroll
        for (int j = 0; j < 4; j++) acc[i][j] = 0.0f;

    for (int k0 = 0; k0 < 256; k0 += 16) {
#pragma unroll
        for (int i = 0; i < 2; i++) {
            int f = tid + i * 256;
            int m = f >> 2;
            int kq = (f & 3) * 4;
            float4 v = *(const float4*)(x + (size_t)(m0 + m) * 256 + k0 + kq);
            Xs[kq + 0][m] = v.x; Xs[kq + 1][m] = v.y;
            Xs[kq + 2][m] = v.z; Xs[kq + 3][m] = v.w;
        }
        {
            int r = tid >> 2;
            int kq = (tid & 3) * 4;
            float4 v = *(const float4*)(W + (size_t)(n0 + r) * 256 + k0 + kq);
            Ws[kq + 0][r] = v.x; Ws[kq + 1][r] = v.y;
            Ws[kq + 2][r] = v.z; Ws[kq + 3][r] = v.w;
        }
        __syncthreads();
#pragma unroll
        for (int k = 0; k < 16; k++) {
            float rm[8], rn[4];
#pragma unroll
            for (int i = 0; i < 8; i++) rm[i] = Xs[k][tm + i];
#pragma unroll
            for (int j = 0; j < 4; j++) rn[j] = Ws[k][tn + j];
#pragma unroll
            for (int i = 0; i < 8; i++)
#pragma unroll
                for (int j = 0; j < 4; j++)
                    acc[i][j] = fmaf(rm[i], rn[j], acc[i][j]);
        }
        __syncthreads();
    }
#pragma unroll
    for (int i = 0; i < 8; i++)
#pragma unroll
        for (int j = 0; j < 4; j++) {
            int r = n0 + tn + j;
            g_zx[(size_t)(m0 + tm + i) * 512 + r] = acc[i][j] + b1[r] + b2[r];
        }
}

// ---------------------------------------------------------------------------
// Layer 0: 2-CTA cluster, split-GEMV with DSMEM-transit overlap, fused fast
// gates. (Structure proven in R15; activations now tanh.approx.)
// ---------------------------------------------------------------------------
__device__ void run_layer0_pair(int rank,
                                const float* __restrict__ Whh,
                                const float* __restrict__ c0,
                                const float* __restrict__ h0,
                                ull* __restrict__ ring,   /* smem [2][64] */
                                float* __restrict__ act   /* smem [128], 16B aligned */) {
    const int tid  = threadIdx.x;
    const int lane = tid & 31;
    const int w    = tid >> 5;
    const int x    = lane & 7;
    const int c    = lane >> 3;
    const int e    = 64 * rank + 8 * w + x;

    ull wo[4][8], wp[4][8];
    const int ownb  = 64 * rank + 16 * c;
    const int peerb = 64 * (1 - rank) + 16 * c;
#pragma unroll
    for (int g = 0; g < 4; g++) {
        const float* row = Whh + (size_t)(g * 128 + e) * 128;
#pragma unroll
        for (int k = 0; k < 8; k++) {
            wo[g][k] = (ull)__float_as_uint(row[ownb + 2 * k]) |
                       ((ull)__float_as_uint(row[ownb + 2 * k + 1]) << 32);
            wp[g][k] = (ull)__float_as_uint(row[peerb + 2 * k]) |
                       ((ull)__float_as_uint(row[peerb + 2 * k + 1]) << 32);
        }
    }

    if (tid < 128) ring[tid] = 0ull;
    if (tid < 128) act[tid] = h0[tid];

    float creg = 0.0f;
    uint32_t peer_addr = 0;
    if (lane < 8) {
        creg = c0[e];
        uint32_t local = smem_u32(&ring[8 * w + x]);
        asm("mapa.shared::cluster.u32 %0, %1, %2;"
            : "=r"(peer_addr) : "r"(local), "r"(1 - rank));
    }
    const uint32_t ring_base = smem_u32(ring);
    __syncthreads();
    cluster_sync_();

    const ull* hv = (const ull*)act;
    const int ou = ownb >> 1;
    const int pu = peerb >> 1;

    for (int t = 0; t < T_STEPS; t++) {
        float zx0 = 0.f, zx1 = 0.f, zx2 = 0.f, zx3 = 0.f;
        if (lane < 8) {
            const float* zp = &g_zx[(size_t)t * 512 + e];
            zx0 = __ldg(zp);       zx1 = __ldg(zp + 128);
            zx2 = __ldg(zp + 256); zx3 = __ldg(zp + 384);
        }

        __syncthreads();              // bar1: act own half (t-1) visible

        ull a0 = 0, a1 = 0, a2 = 0, a3 = 0;
        {
            ull h[8];
#pragma unroll
            for (int k = 0; k < 4; k++)
                ((ulonglong2*)h)[k] = ((const ulonglong2*)(hv + ou))[k];
#pragma unroll
            for (int k = 0; k < 8; k++) {
                a0 = fma2_(wo[0][k], h[k], a0);
                a1 = fma2_(wo[1][k], h[k], a1);
                a2 = fma2_(wo[2][k], h[k], a2);
                a3 = fma2_(wo[3][k], h[k], a3);
            }
        }

        if (w == 7 && t > 0) {        // poll peer half during transit window
            const uint32_t sb = ring_base + (((t - 1) & 1) ? 512u : 0u);
            const unsigned ex = (unsigned)(t + 1);
            ull v0 = lds_vol(sb + lane * 8);
            ull v1 = lds_vol(sb + (lane + 32) * 8);
            while ((unsigned)(v0 >> 32) != ex) v0 = lds_vol(sb + lane * 8);
            while ((unsigned)(v1 >> 32) != ex) v1 = lds_vol(sb + (lane + 32) * 8);
            act[64 * (1 - rank) + lane]      = __uint_as_float((unsigned)v0);
            act[64 * (1 - rank) + lane + 32] = __uint_as_float((unsigned)v1);
        }

        __syncthreads();              // bar2: act peer half (t-1) visible

        {
            ull h[8];
#pragma unroll
            for (int k = 0; k < 4; k++)
                ((ulonglong2*)h)[k] = ((const ulonglong2*)(hv + pu))[k];
#pragma unroll
            for (int k = 0; k < 8; k++) {
                a0 = fma2_(wp[0][k], h[k], a0);
                a1 = fma2_(wp[1][k], h[k], a1);
                a2 = fma2_(wp[2][k], h[k], a2);
                a3 = fma2_(wp[3][k], h[k], a3);
            }
        }

        float s0 = __uint_as_float((unsigned)a0) + __uint_as_float((unsigned)(a0 >> 32));
        float s1 = __uint_as_float((unsigned)a1) + __uint_as_float((unsigned)(a1 >> 32));
        float s2 = __uint_as_float((unsigned)a2) + __uint_as_float((unsigned)(a2 >> 32));
        float s3 = __uint_as_float((unsigned)a3) + __uint_as_float((unsigned)(a3 >> 32));
        s0 += __shfl_xor_sync(0xffffffffu, s0, 8);
        s1 += __shfl_xor_sync(0xffffffffu, s1, 8);
        s2 += __shfl_xor_sync(0xffffffffu, s2, 8);
        s3 += __shfl_xor_sync(0xffffffffu, s3, 8);
        s0 += __shfl_xor_sync(0xffffffffu, s0, 16);
        s1 += __shfl_xor_sync(0xffffffffu, s1, 16);
        s2 += __shfl_xor_sync(0xffffffffu, s2, 16);
        s3 += __shfl_xor_sync(0xffffffffu, s3, 16);

        if (lane < 8) {
            float ig = sig_ap(s0 + zx0);
            float fg = sig_ap(s1 + zx1);
            float gg = tanh_ap(s2 + zx2);
            float og = sig_ap(s3 + zx3);
            float c2 = fg * creg + ig * gg;
            creg = c2;
            float h2 = og * tanh_ap(c2);

            act[e] = h2;
            if (t < T_STEPS - 1)
                sts_cluster(peer_addr + ((t & 1) ? 512u : 0u),
                            pack_hv(h2, (unsigned)(t + 2)));
            str(g_hist0 + (size_t)(t + OFF) * 128 + e,
                pack_hv(h2, (unsigned)(t + OFF + 1)));
        }
    }

    cluster_sync_();
}

// ---------------------------------------------------------------------------
// Upper layers (1..3): software-pipelined prestage — next step's tagged loads
// are issued right after the barrier, so their L2 latency hides under this
// step's GEMV/gates. One barrier per step; double-buffered act.
// ---------------------------------------------------------------------------
template <int DIN, int DOUT, int G, int DILN, int MODE>
__device__ void run_layer_coop(int cta,
                               const float* __restrict__ Wih,
                               const float* __restrict__ Whh,
                               const float* __restrict__ bih,
                               const float* __restrict__ bhh,
                               const float* __restrict__ c0,
                               const ull* __restrict__ hin,
                               ull* __restrict__ hown,
                               float* __restrict__ out,
                               float* __restrict__ act /* [2][COLS] */) {
    constexpr int CHUNK = DOUT / G;       // 8
    constexpr int COLS  = DIN + DOUT;     // 256 or 384
    constexpr int CPL   = COLS / 32;      // 8 or 12
    static_assert(CHUNK == 8, "8 warps x 1 elem");

    const int tid  = threadIdx.x;
    const int lane = tid & 31;
    const int w    = tid >> 5;
    const int e    = cta * CHUNK + w;

    float wreg[4][CPL];
#pragma unroll
    for (int g = 0; g < 4; g++) {
        int zr = g * DOUT + e;
#pragma unroll
        for (int k = 0; k < CPL; k++) {
            int j = lane + 32 * k;
            wreg[g][k] = (j < DIN) ? Wih[(size_t)zr * DIN + j]
                                   : Whh[(size_t)zr * DOUT + (j - DIN)];
        }
    }
    float b0 = 0, b1 = 0, b2 = 0, b3 = 0;
    float creg[DILN];
    if (lane == 0) {
        b0 = bih[0 * DOUT + e] + bhh[0 * DOUT + e];
        b1 = bih[1 * DOUT + e] + bhh[1 * DOUT + e];
        b2 = bih[2 * DOUT + e] + bhh[2 * DOUT + e];
        b3 = bih[3 * DOUT + e] + bhh[3 * DOUT + e];
#pragma unroll
        for (int k = 0; k < DILN; k++) creg[k] = c0[k * DOUT + e];
    }

    // ---- staging slots: idx0 = tid, idx1 = tid+256 (if COLS>256) ----
    const int idx0 = tid;
    const int idx1 = tid + 256;
    constexpr bool HAS1 = (COLS > 256);
    const ull* q0; unsigned ex0; int inc0;
    const ull* q1 = nullptr; unsigned ex1 = 0; int inc1 = 0;
    if (idx0 < DIN) { q0 = hin + (size_t)OFF * DIN + idx0;
                      ex0 = OFF + 1; inc0 = DIN; }
    else            { q0 = hown + (size_t)(OFF - DILN) * DOUT + (idx0 - DIN);
                      ex0 = OFF - DILN + 1; inc0 = DOUT; }
    if (HAS1 && idx1 < COLS) {
        if (idx1 < DIN) { q1 = hin + (size_t)OFF * DIN + idx1;
                          ex1 = OFF + 1; inc1 = DIN; }
        else            { q1 = hown + (size_t)(OFF - DILN) * DOUT + (idx1 - DIN);
                          ex1 = OFF - DILN + 1; inc1 = DOUT; }
    }
    ull v0 = ldr(q0);
    ull v1 = (HAS1 && idx1 < COLS) ? ldr(q1) : 0ull;

    for (int tb = 0; tb < T_STEPS; tb += DILN) {
#pragma unroll
        for (int kk = 0; kk < DILN; kk++) {
            const int t = tb + kk;
            float* buf = act + (t & 1) * COLS;
            // finish staging step t (usually already landed)
            while ((unsigned)(v0 >> 32) != ex0) v0 = ldr(q0);
            buf[idx0] = __uint_as_float((unsigned)v0);
            if (HAS1 && idx1 < COLS) {
                while ((unsigned)(v1 >> 32) != ex1) v1 = ldr(q1);
                buf[idx1] = __uint_as_float((unsigned)v1);
            }
            __syncthreads();

            // prestage step t+1 — latency hides under compute below
            q0 += inc0; ex0 += 1; v0 = ldr(q0);
            if (HAS1 && idx1 < COLS) { q1 += inc1; ex1 += 1; v1 = ldr(q1); }

            float a0 = 0, a1 = 0, a2 = 0, a3 = 0;
#pragma unroll
            for (int k = 0; k < CPL; k++) {
                float a = buf[lane + 32 * k];
                a0 = fmaf(wreg[0][k], a, a0);
                a1 = fmaf(wreg[1][k], a, a1);
                a2 = fmaf(wreg[2][k], a, a2);
                a3 = fmaf(wreg[3][k], a, a3);
            }
#pragma unroll
            for (int d = 16; d > 0; d >>= 1) {
                a0 += __shfl_xor_sync(0xffffffffu, a0, d);
                a1 += __shfl_xor_sync(0xffffffffu, a1, d);
                a2 += __shfl_xor_sync(0xffffffffu, a2, d);
                a3 += __shfl_xor_sync(0xffffffffu, a3, d);
            }
            if (lane == 0) {
                float ig = sig_ap(a0 + b0);
                float fg = sig_ap(a1 + b1);
                float gg = tanh_ap(a2 + b2);
                float og = sig_ap(a3 + b3);
                float c2 = fg * creg[kk] + ig * gg;
                creg[kk] = c2;
                float h2 = og * tanh_ap(c2);
                str(hown + (size_t)(t + OFF) * DOUT + e,
                    pack_hv(h2, (unsigned)(t + OFF + 1)));
                if (MODE == 2) out[(size_t)t * 256 + e] = h2;
            }
        }
    }
}

// ---------------------------------------------------------------------------
struct DP {
    const float *Whh0, *h00, *c00;
    const float *Wih1, *Whh1, *bih1, *bhh1, *c01;
    const float *Wih2, *Whh2, *bih2, *bhh2, *c02;
    const float *Wih3, *Whh3, *bih3, *bhh3, *c03;
    float* out;
};

// 66 CTAs, cluster 2: {0,1}=L0 pair; [2,18)=L1; [18,34)=L2; [34,66)=L3.
__global__ void __launch_bounds__(256, 1) __cluster_dims__(2, 1, 1)
drnn_kernel(DP p) {
    __shared__ ull ring[2 * 64];
    __shared__ __align__(16) float act0[128];
    __shared__ float act[2 * 384];
    int b = blockIdx.x;
    if (b < 2) {
        run_layer0_pair(b, p.Whh0, p.c00, p.h00, ring, act0);
    } else if (b < 18) {
        run_layer_coop<128, 128, 16, 2, 0>(b - 2, p.Wih1, p.Whh1, p.bih1,
                                           p.bhh1, p.c01, g_hist0, g_hist1,
                                           nullptr, act);
    } else if (b < 34) {
        run_layer_coop<128, 128, 16, 4, 0>(b - 18, p.Wih2, p.Whh2, p.bih2,
                                           p.bhh2, p.c02, g_hist1, g_hist2,
                                           nullptr, act);
    } else {
        run_layer_coop<128, 256, 32, 8, 2>(b - 34, p.Wih3, p.Whh3, p.bih3,
                                           p.bhh3, p.c03, g_hist2, g_hist3,
                                           p.out, act);
    }
}

// ---------------------------------------------------------------------------
extern "C" void kernel_launch(void* const* d_in, const int* in_sizes, int n_in,
                              void* d_out, int out_size) {
    // detect interleaved (x,[W,U,bi,bh,h0,c0]*4) vs grouped (x, W*16, states*8)
    int iW[4], iU[4], ibi[4], ibh[4], ih[4], ic[4];
    if (in_sizes[5] == 128) {            // interleaved
        for (int i = 0; i < 4; i++) {
            int base = 1 + i * 6;
            iW[i] = base; iU[i] = base + 1; ibi[i] = base + 2; ibh[i] = base + 3;
            ih[i] = base + 4; ic[i] = base + 5;
        }
    } else {                             // grouped
        for (int i = 0; i < 4; i++) {
            iW[i] = 1 + 4 * i; iU[i] = 2 + 4 * i;
            ibi[i] = 3 + 4 * i; ibh[i] = 4 + 4 * i;
            ih[i] = 17 + 2 * i; ic[i] = 18 + 2 * i;
        }
    }

    const float* x = (const float*)d_in[0];

    init_hist_kernel<<<256, 256>>>((const float*)d_in[ih[0]],
                                   (const float*)d_in[ih[1]],
                                   (const float*)d_in[ih[2]],
                                   (const float*)d_in[ih[3]]);

    dim3 g(16, 8);
    xproj_kernel<<<g, 256>>>(x, (const float*)d_in[iW[0]],
                             (const float*)d_in[ibi[0]],
                             (const float*)d_in[ibh[0]]);

    DP p;
    p.Whh0 = (const float*)d_in[iU[0]];
    p.h00  = (const float*)d_in[ih[0]];
    p.c00  = (const float*)d_in[ic[0]];
    p.Wih1 = (const float*)d_in[iW[1]]; p.Whh1 = (const float*)d_in[iU[1]];
    p.bih1 = (const float*)d_in[ibi[1]]; p.bhh1 = (const float*)d_in[ibh[1]];
    p.c01  = (const float*)d_in[ic[1]];
    p.Wih2 = (const float*)d_in[iW[2]]; p.Whh2 = (const float*)d_in[iU[2]];
    p.bih2 = (const float*)d_in[ibi[2]]; p.bhh2 = (const float*)d_in[ibh[2]];
    p.c02  = (const float*)d_in[ic[2]];
    p.Wih3 = (const float*)d_in[iW[3]]; p.Whh3 = (const float*)d_in[iU[3]];
    p.bih3 = (const float*)d_in[ibi[3]]; p.bhh3 = (const float*)d_in[ibh[3]];
    p.c03  = (const float*)d_in[ic[3]];
    p.out  = (float*)d_out;

    drnn_kernel<<<66, 256>>>(p);
}